// round 2
// baseline (speedup 1.0000x reference)
#include <cuda_runtime.h>
#include <math.h>

#define TN 200
#define BN 256
#define EN 300
#define HN 512
#define GN 1536            // 3*H
#define MN (TN*BN)         // 51200

typedef unsigned long long ull;

// ---------------- static device scratch ----------------
__device__ float g_xproj[(size_t)2 * TN * BN * GN];   // [dir][t*B+b][3H]
__device__ float g_out  [(size_t)2 * TN * BN * HN];   // [dir][t][b][H]
__device__ float g_h    [2 * 2 * BN * HN];            // [dir][pingpong][b][H]
__device__ float g_v    [2 * HN];
__device__ float g_cbias;
__device__ int   g_inv  [BN];
__device__ float g_logits[BN * TN];
__device__ float g_att   [BN * TN];

// ---------------- f32x2 helpers ----------------
__device__ __forceinline__ ull fma2(ull a, ull b, ull c) {
    ull d;
    asm("fma.rn.f32x2 %0, %1, %2, %3;" : "=l"(d) : "l"(a), "l"(b), "l"(c));
    return d;
}
__device__ __forceinline__ ull pack2(float x, float y) {
    ull d;
    asm("mov.b64 %0, {%1, %2};" : "=l"(d) : "f"(x), "f"(y));
    return d;
}
union f4u { float4 f; ull u[2]; float s[4]; };
union uf2 { ull u; float2 f; };

__device__ __forceinline__ float sigf(float x) {
    return 1.0f / (1.0f + __expf(-x));
}
__device__ __forceinline__ float tanhfast(float x) {
    float e = __expf(2.0f * x);
    return (e - 1.0f) / (e + 1.0f);
}

// ---------------- init ----------------
__global__ void init_kernel() {
    int i = blockIdx.x * blockDim.x + threadIdx.x;
    if (i < 2 * 2 * BN * HN) g_h[i] = 0.0f;
}

// ---------------- prep ----------------
__global__ void prep_kernel(const float* __restrict__ Wattn,
                            const float* __restrict__ battn,
                            const float* __restrict__ Wcomb,
                            const int*   __restrict__ sidx) {
    int tid = threadIdx.x;   // 1024
    float s = 0.0f;
    for (int m = 0; m < 2 * HN; m++)
        s += Wcomb[m] * Wattn[(size_t)m * (2 * HN) + tid];
    g_v[tid] = s;
    if (tid == 0) {
        float c = 0.0f;
        for (int m = 0; m < 2 * HN; m++) c += Wcomb[m] * battn[m];
        g_cbias = c;
    }
    if (tid < BN) g_inv[sidx[tid]] = tid;
}

// ---------------- input projection GEMM (f32x2, reg double-buffered) -------------------
// C[m][g] = sum_e inp[m][e] * W[g][e] + b[g].  128x128 tile, 8x8/thread as 8x4 pairs.
__global__ __launch_bounds__(256) void proj_kernel(const float* __restrict__ inp,
                                                   const float* __restrict__ Wf,
                                                   const float* __restrict__ bf,
                                                   const float* __restrict__ Wb,
                                                   const float* __restrict__ bb) {
    __shared__ __align__(16) float As[8][128];
    __shared__ __align__(16) float Ws[8][128];

    int dir = blockIdx.z;
    const float* W    = dir ? Wb : Wf;
    const float* bias = dir ? bb : bf;
    int m0 = blockIdx.x * 128;
    int g0 = blockIdx.y * 128;
    int tid = threadIdx.x;
    int tx = tid & 15, ty = tid >> 4;
    int lr = tid >> 1, lk = (tid & 1) * 4;

    ull acc[8][4];
#pragma unroll
    for (int i = 0; i < 8; i++)
#pragma unroll
        for (int p = 0; p < 4; p++) acc[i][p] = 0ULL;

    const float* Arow = inp + (size_t)(m0 + lr) * EN;
    const float* Wrow = W   + (size_t)(g0 + lr) * EN;

    const int NCH = (EN + 7) / 8;   // 38
    f4u ra, rw;

    // load chunk 0
    {
        int k = lk;
        if (k + 3 < EN) { ra.f = *(const float4*)&Arow[k]; rw.f = *(const float4*)&Wrow[k]; }
        else { ra.f = make_float4(0,0,0,0); rw.f = make_float4(0,0,0,0); }
    }

    for (int c = 0; c < NCH; c++) {
#pragma unroll
        for (int u = 0; u < 4; u++) {
            As[lk + u][lr] = ra.s[u];
            Ws[lk + u][lr] = rw.s[u];
        }
        __syncthreads();
        if (c + 1 < NCH) {
            int k = (c + 1) * 8 + lk;
            if (k + 3 < EN) { ra.f = *(const float4*)&Arow[k]; rw.f = *(const float4*)&Wrow[k]; }
            else { ra.f = make_float4(0,0,0,0); rw.f = make_float4(0,0,0,0); }
        }
#pragma unroll
        for (int kk = 0; kk < 8; kk++) {
            f4u a0, a1, b0, b1;
            a0.f = *(const float4*)&As[kk][ty * 8];
            a1.f = *(const float4*)&As[kk][ty * 8 + 4];
            b0.f = *(const float4*)&Ws[kk][tx * 8];
            b1.f = *(const float4*)&Ws[kk][tx * 8 + 4];
            ull bv[4] = {b0.u[0], b0.u[1], b1.u[0], b1.u[1]};
            float av[8] = {a0.s[0], a0.s[1], a0.s[2], a0.s[3],
                           a1.s[0], a1.s[1], a1.s[2], a1.s[3]};
#pragma unroll
            for (int i = 0; i < 8; i++) {
                ull ap = pack2(av[i], av[i]);
#pragma unroll
                for (int p = 0; p < 4; p++)
                    acc[i][p] = fma2(ap, bv[p], acc[i][p]);
            }
        }
        __syncthreads();
    }

    f4u bl0, bl1;
    bl0.f = *(const float4*)&bias[g0 + tx * 8];
    bl1.f = *(const float4*)&bias[g0 + tx * 8 + 4];

#pragma unroll
    for (int i = 0; i < 8; i++) {
        int m = m0 + ty * 8 + i;
        float* outp = g_xproj + ((size_t)dir * MN + m) * GN + g0 + tx * 8;
        f4u o0, o1;
#pragma unroll
        for (int p = 0; p < 2; p++) {
            uf2 v; v.u = acc[i][p];
            o0.s[2 * p]     = v.f.x + bl0.s[2 * p];
            o0.s[2 * p + 1] = v.f.y + bl0.s[2 * p + 1];
        }
#pragma unroll
        for (int p = 0; p < 2; p++) {
            uf2 v; v.u = acc[i][p + 2];
            o1.s[2 * p]     = v.f.x + bl1.s[2 * p];
            o1.s[2 * p + 1] = v.f.y + bl1.s[2 * p + 1];
        }
        *(float4*)&outp[0] = o0.f;
        *(float4*)&outp[4] = o1.f;
    }
}

// ---------------- GRU step (f32x2 GEMM + fused pointwise) ----------------
// Block tile: 64 j-cols x 32 batch x 3 gates. 256 threads.
// Per thread: 4 j (2 pairs) x 2 b x 3 gates = 12 f32x2 accumulators.
#define KC 32
__global__ __launch_bounds__(256) void step_kernel(const float* __restrict__ Whf,
                                                   const float* __restrict__ bhf,
                                                   const float* __restrict__ Whb,
                                                   const float* __restrict__ bhb,
                                                   const int*   __restrict__ slen,
                                                   int t) {
    __shared__ __align__(16) float ws[3][KC][68];   // [gate][kk][j] padded
    __shared__ float hs[KC][33];                    // [kk][b] padded

    int dir = blockIdx.z;
    int tt  = dir ? (TN - 1 - t) : t;
    const float* W  = dir ? Whb : Whf;
    const float* bh = dir ? bhb : bhf;
    int j0 = blockIdx.x * 64;
    int b0 = blockIdx.y * 32;
    int tid = threadIdx.x;
    int w = tid >> 5, l = tid & 31;
    int wj = w & 1, wb = w >> 1;       // wb 0..3
    int jg = l & 7, bg = l >> 3;       // bg 0..3
    int jt = wj * 32 + jg * 4;         // local j base (0..60)
    int bl = wb * 8 + bg * 2;          // local b base (0..30)
    int j  = j0 + jt;
    int pp = t & 1;

    const float* hsrc = g_h + (size_t)(dir * 2 + pp)       * BN * HN;
    float*       hdst = g_h + (size_t)(dir * 2 + (pp ^ 1)) * BN * HN;

    ull acc[3][2][2];
#pragma unroll
    for (int g = 0; g < 3; g++)
#pragma unroll
        for (int i = 0; i < 2; i++)
#pragma unroll
            for (int p = 0; p < 2; p++) acc[g][i][p] = 0ULL;

    // per-thread load indices for weight staging: 6 float4 per chunk
    int wg[6], wjj[6], wf4[6];
#pragma unroll
    for (int p = 0; p < 6; p++) {
        int idx = tid + 256 * p;       // 0..1535
        wg[p]  = idx >> 9;             // gate
        wjj[p] = (idx & 511) >> 3;     // j row 0..63
        wf4[p] = idx & 7;              // k-float4 0..7
    }
    int hb  = tid >> 3;                // 0..31
    int hf4 = tid & 7;                 // 0..7

    f4u wreg[6], hreg;

    // load chunk 0
#pragma unroll
    for (int p = 0; p < 6; p++)
        wreg[p].f = *(const float4*)&W[(size_t)(wg[p] * HN + j0 + wjj[p]) * HN + wf4[p] * 4];
    hreg.f = *(const float4*)&hsrc[(size_t)(b0 + hb) * HN + hf4 * 4];

    for (int c = 0; c < HN / KC; c++) {
#pragma unroll
        for (int p = 0; p < 6; p++)
#pragma unroll
            for (int u = 0; u < 4; u++)
                ws[wg[p]][wf4[p] * 4 + u][wjj[p]] = wreg[p].s[u];
#pragma unroll
        for (int u = 0; u < 4; u++)
            hs[hf4 * 4 + u][hb] = hreg.s[u];
        __syncthreads();

        if (c + 1 < HN / KC) {
            int k0 = (c + 1) * KC;
#pragma unroll
            for (int p = 0; p < 6; p++)
                wreg[p].f = *(const float4*)&W[(size_t)(wg[p] * HN + j0 + wjj[p]) * HN + k0 + wf4[p] * 4];
            hreg.f = *(const float4*)&hsrc[(size_t)(b0 + hb) * HN + k0 + hf4 * 4];
        }

#pragma unroll
        for (int kk = 0; kk < KC; kk++) {
            float h0 = hs[kk][bl];
            float h1 = hs[kk][bl + 1];
            ull h2a = pack2(h0, h0);
            ull h2b = pack2(h1, h1);
#pragma unroll
            for (int g = 0; g < 3; g++) {
                f4u wv;
                wv.f = *(const float4*)&ws[g][kk][jt];
                acc[g][0][0] = fma2(h2a, wv.u[0], acc[g][0][0]);
                acc[g][0][1] = fma2(h2a, wv.u[1], acc[g][0][1]);
                acc[g][1][0] = fma2(h2b, wv.u[0], acc[g][1][0]);
                acc[g][1][1] = fma2(h2b, wv.u[1], acc[g][1][1]);
            }
        }
        __syncthreads();
    }

    // biases (4 j each gate)
    f4u br4, bz4, bn4;
    br4.f = *(const float4*)&bh[j];
    bz4.f = *(const float4*)&bh[HN + j];
    bn4.f = *(const float4*)&bh[2 * HN + j];

#pragma unroll
    for (int i = 0; i < 2; i++) {
        int row = b0 + bl + i;
        const float* xp = g_xproj + ((size_t)dir * MN + (size_t)tt * BN + row) * GN;
        f4u xr, xz, xn, hold;
        xr.f   = *(const float4*)&xp[j];
        xz.f   = *(const float4*)&xp[HN + j];
        xn.f   = *(const float4*)&xp[2 * HN + j];
        hold.f = *(const float4*)&hsrc[(size_t)row * HN + j];
        bool m = tt < slen[row];

        float hr[4], hz[4], hn_[4];
#pragma unroll
        for (int p = 0; p < 2; p++) {
            uf2 v0, v1, v2;
            v0.u = acc[0][i][p]; v1.u = acc[1][i][p]; v2.u = acc[2][i][p];
            hr[2 * p] = v0.f.x;  hr[2 * p + 1] = v0.f.y;
            hz[2 * p] = v1.f.x;  hz[2 * p + 1] = v1.f.y;
            hn_[2 * p] = v2.f.x; hn_[2 * p + 1] = v2.f.y;
        }

        f4u hnew, onew;
#pragma unroll
        for (int q = 0; q < 4; q++) {
            float r = sigf(xr.s[q] + hr[q] + br4.s[q]);
            float z = sigf(xz.s[q] + hz[q] + bz4.s[q]);
            float n = tanhfast(xn.s[q] + r * (hn_[q] + bn4.s[q]));
            float hv = (1.0f - z) * n + z * hold.s[q];
            hnew.s[q] = m ? hv : hold.s[q];
            onew.s[q] = m ? hv : 0.0f;
        }
        *(float4*)&hdst[(size_t)row * HN + j] = hnew.f;
        *(float4*)&g_out[(((size_t)dir * TN + tt) * BN + row) * HN + j] = onew.f;
    }
}

// ---------------- logits ----------------
__global__ void logits_kernel(const int* __restrict__ sidx) {
    int jb = blockIdx.x;
    int t  = blockIdx.y;
    int tid = threadIdx.x;    // 128

    const float* of = g_out + (((size_t)0 * TN + t) * BN + jb) * HN;
    const float* ob = g_out + (((size_t)1 * TN + t) * BN + jb) * HN;
    float s = 0.0f;
    for (int h = tid; h < HN; h += 128)
        s += of[h] * g_v[h] + ob[h] * g_v[HN + h];

    for (int o = 16; o > 0; o >>= 1) s += __shfl_down_sync(0xffffffff, s, o);
    __shared__ float red[4];
    if ((tid & 31) == 0) red[tid >> 5] = s;
    __syncthreads();
    if (tid == 0) {
        float tot = red[0] + red[1] + red[2] + red[3] + g_cbias;
        g_logits[(size_t)sidx[jb] * TN + t] = tot;
    }
}

// ---------------- softmax ----------------
__global__ void softmax_kernel(const int* __restrict__ seqlen) {
    int b = blockIdx.x;
    int tid = threadIdx.x;    // 256
    int len = seqlen[b];
    bool valid = (tid < TN) && (tid < len);
    float l = valid ? g_logits[(size_t)b * TN + tid] : -1e30f;

    __shared__ float sm[256];
    sm[tid] = l;
    __syncthreads();
    for (int s = 128; s > 0; s >>= 1) {
        if (tid < s) sm[tid] = fmaxf(sm[tid], sm[tid + s]);
        __syncthreads();
    }
    float mx = sm[0];
    __syncthreads();
    float e = valid ? expf(l - mx) : 0.0f;
    sm[tid] = e;
    __syncthreads();
    for (int s = 128; s > 0; s >>= 1) {
        if (tid < s) sm[tid] += sm[tid + s];
        __syncthreads();
    }
    float inv = 1.0f / sm[0];
    if (tid < TN) g_att[(size_t)b * TN + tid] = e * inv;
}

// ---------------- weighted sum ----------------
__global__ void wsum_kernel(float* __restrict__ out) {
    int ob  = blockIdx.x;
    int h   = blockIdx.y * 256 + threadIdx.x;
    int jb  = g_inv[ob];
    int d   = (h < HN) ? 0 : 1;
    int hh  = (h < HN) ? h : (h - HN);

    const float* av   = g_att + (size_t)ob * TN;
    const float* base = g_out + ((size_t)d * TN * BN + jb) * HN + hh;

    float acc = 0.0f;
    for (int t = 0; t < TN; t++)
        acc += av[t] * base[(size_t)t * BN * HN];
    out[(size_t)ob * (2 * HN) + h] = acc;
}

// ---------------- launch ----------------
extern "C" void kernel_launch(void* const* d_in, const int* in_sizes, int n_in,
                              void* d_out, int out_size) {
    const float* inp    = (const float*)d_in[0];
    const float* Wih_f  = (const float*)d_in[1];
    const float* Whh_f  = (const float*)d_in[2];
    const float* bih_f  = (const float*)d_in[3];
    const float* bhh_f  = (const float*)d_in[4];
    const float* Wih_b  = (const float*)d_in[5];
    const float* Whh_b  = (const float*)d_in[6];
    const float* bih_b  = (const float*)d_in[7];
    const float* bhh_b  = (const float*)d_in[8];
    const float* Wattn  = (const float*)d_in[9];
    const float* battn  = (const float*)d_in[10];
    const float* Wcomb  = (const float*)d_in[11];
    const int*   slen_s = (const int*)d_in[12];
    const int*   sidx   = (const int*)d_in[13];
    const int*   seqlen = (const int*)d_in[14];
    float* out = (float*)d_out;

    init_kernel<<<(2 * 2 * BN * HN + 255) / 256, 256>>>();
    prep_kernel<<<1, 1024>>>(Wattn, battn, Wcomb, sidx);
    proj_kernel<<<dim3(MN / 128, GN / 128, 2), 256>>>(inp, Wih_f, bih_f, Wih_b, bih_b);
    for (int t = 0; t < TN; t++)
        step_kernel<<<dim3(HN / 64, BN / 32, 2), 256>>>(Whh_f, bhh_f, Whh_b, bhh_b, slen_s, t);
    logits_kernel<<<dim3(BN, TN), 128>>>(sidx);
    softmax_kernel<<<BN, 256>>>(seqlen);
    wsum_kernel<<<dim3(BN, 4), 256>>>(out);
}

// round 3
// speedup vs baseline: 1.6856x; 1.6856x over previous
#include <cuda_runtime.h>
#include <cuda_bf16.h>
#include <math.h>

#define TN 200
#define BN 256
#define EN 300
#define HN 512
#define GN 1536            // 3*H
#define MN (TN*BN)         // 51200

typedef unsigned long long ull;
typedef unsigned int u32;

// ---------------- static device scratch ----------------
__device__ __align__(128) float g_xproj[(size_t)2 * TN * BN * GN];   // [dir][t*B+b][3H]
__device__ __align__(128) float g_out  [(size_t)2 * TN * BN * HN];   // [dir][t][b][H]
__device__ __align__(128) float g_h    [2 * 2 * BN * HN];            // [dir][pp][b][H] fp32
__device__ __align__(128) __nv_bfloat16 g_hbh[2 * 2 * BN * HN];      // h bf16 hi
__device__ __align__(128) __nv_bfloat16 g_hbl[2 * 2 * BN * HN];      // h bf16 lo
__device__ __align__(128) __nv_bfloat16 g_Wbh[2 * GN * HN];          // W_hh bf16 hi
__device__ __align__(128) __nv_bfloat16 g_Wbl[2 * GN * HN];          // W_hh bf16 lo
__device__ float g_v    [2 * HN];
__device__ float g_cbias;
__device__ int   g_inv  [BN];
__device__ float g_logits[BN * TN];
__device__ float g_att   [BN * TN];

// ---------------- helpers ----------------
__device__ __forceinline__ ull fma2(ull a, ull b, ull c) {
    ull d;
    asm("fma.rn.f32x2 %0, %1, %2, %3;" : "=l"(d) : "l"(a), "l"(b), "l"(c));
    return d;
}
__device__ __forceinline__ ull pack2(float x, float y) {
    ull d;
    asm("mov.b64 %0, {%1, %2};" : "=l"(d) : "f"(x), "f"(y));
    return d;
}
union f4u { float4 f; ull u[2]; float s[4]; };
union uf2 { ull u; float2 f; };

__device__ __forceinline__ float sigf(float x) { return 1.0f / (1.0f + __expf(-x)); }
__device__ __forceinline__ float tanhfast(float x) {
    float e = __expf(2.0f * x);
    return (e - 1.0f) / (e + 1.0f);
}
__device__ __forceinline__ u32 smem_u32(const void* p) {
    return (u32)__cvta_generic_to_shared(p);
}
__device__ __forceinline__ void cpa16(u32 s, const void* g) {
    asm volatile("cp.async.cg.shared.global [%0], [%1], 16;" :: "r"(s), "l"(g));
}
__device__ __forceinline__ void cpa_commit() { asm volatile("cp.async.commit_group;"); }
__device__ __forceinline__ void cpa_wait0()  { asm volatile("cp.async.wait_group 0;"); }

__device__ __forceinline__ void ldsm4(u32 addr, u32& r0, u32& r1, u32& r2, u32& r3) {
    asm volatile("ldmatrix.sync.aligned.m8n8.x4.shared.b16 {%0,%1,%2,%3}, [%4];"
                 : "=r"(r0), "=r"(r1), "=r"(r2), "=r"(r3) : "r"(addr));
}
__device__ __forceinline__ void ldsm2(u32 addr, u32& r0, u32& r1) {
    asm volatile("ldmatrix.sync.aligned.m8n8.x2.shared.b16 {%0,%1}, [%2];"
                 : "=r"(r0), "=r"(r1) : "r"(addr));
}
__device__ __forceinline__ void mma_bf16(float* d, const u32* a, const u32* b) {
    asm volatile("mma.sync.aligned.m16n8k16.row.col.f32.bf16.bf16.f32 "
                 "{%0,%1,%2,%3}, {%4,%5,%6,%7}, {%8,%9}, {%0,%1,%2,%3};"
                 : "+f"(d[0]), "+f"(d[1]), "+f"(d[2]), "+f"(d[3])
                 : "r"(a[0]), "r"(a[1]), "r"(a[2]), "r"(a[3]), "r"(b[0]), "r"(b[1]));
}
__device__ __forceinline__ void split_bf16(float x, __nv_bfloat16& hi, __nv_bfloat16& lo) {
    hi = __float2bfloat16(x);
    lo = __float2bfloat16(x - __bfloat162float(hi));
}

// ---------------- init: zero hidden state (fp32 + bf16 pair) ----------------
__global__ void init_kernel() {
    int i = blockIdx.x * blockDim.x + threadIdx.x;
    if (i < 2 * 2 * BN * HN) {
        g_h[i]   = 0.0f;
        g_hbh[i] = __float2bfloat16(0.0f);
        g_hbl[i] = __float2bfloat16(0.0f);
    }
}

// ---------------- convert W_hh to bf16 hi/lo ----------------
__global__ void convw_kernel(const float* __restrict__ Whf,
                             const float* __restrict__ Whb) {
    int i = blockIdx.x * blockDim.x + threadIdx.x;
    const int N = GN * HN;
    if (i < 2 * N) {
        float x = (i < N) ? Whf[i] : Whb[i - N];
        __nv_bfloat16 hi, lo;
        split_bf16(x, hi, lo);
        g_Wbh[i] = hi;
        g_Wbl[i] = lo;
    }
}

// ---------------- prep ----------------
__global__ void prep_kernel(const float* __restrict__ Wattn,
                            const float* __restrict__ battn,
                            const float* __restrict__ Wcomb,
                            const int*   __restrict__ sidx) {
    int tid = threadIdx.x;   // 1024
    float s = 0.0f;
    for (int m = 0; m < 2 * HN; m++)
        s += Wcomb[m] * Wattn[(size_t)m * (2 * HN) + tid];
    g_v[tid] = s;
    if (tid == 0) {
        float c = 0.0f;
        for (int m = 0; m < 2 * HN; m++) c += Wcomb[m] * battn[m];
        g_cbias = c;
    }
    if (tid < BN) g_inv[sidx[tid]] = tid;
}

// ---------------- input projection GEMM (f32x2, from R1/R2) ----------------
__global__ __launch_bounds__(256) void proj_kernel(const float* __restrict__ inp,
                                                   const float* __restrict__ Wf,
                                                   const float* __restrict__ bf,
                                                   const float* __restrict__ Wb,
                                                   const float* __restrict__ bb) {
    __shared__ __align__(16) float As[8][128];
    __shared__ __align__(16) float Ws[8][128];

    int dir = blockIdx.z;
    const float* W    = dir ? Wb : Wf;
    const float* bias = dir ? bb : bf;
    int m0 = blockIdx.x * 128;
    int g0 = blockIdx.y * 128;
    int tid = threadIdx.x;
    int tx = tid & 15, ty = tid >> 4;
    int lr = tid >> 1, lk = (tid & 1) * 4;

    ull acc[8][4];
#pragma unroll
    for (int i = 0; i < 8; i++)
#pragma unroll
        for (int p = 0; p < 4; p++) acc[i][p] = 0ULL;

    const float* Arow = inp + (size_t)(m0 + lr) * EN;
    const float* Wrow = W   + (size_t)(g0 + lr) * EN;

    const int NCH = (EN + 7) / 8;   // 38
    f4u ra, rw;
    {
        int k = lk;
        if (k + 3 < EN) { ra.f = *(const float4*)&Arow[k]; rw.f = *(const float4*)&Wrow[k]; }
        else { ra.f = make_float4(0,0,0,0); rw.f = make_float4(0,0,0,0); }
    }

    for (int c = 0; c < NCH; c++) {
#pragma unroll
        for (int u = 0; u < 4; u++) {
            As[lk + u][lr] = ra.s[u];
            Ws[lk + u][lr] = rw.s[u];
        }
        __syncthreads();
        if (c + 1 < NCH) {
            int k = (c + 1) * 8 + lk;
            if (k + 3 < EN) { ra.f = *(const float4*)&Arow[k]; rw.f = *(const float4*)&Wrow[k]; }
            else { ra.f = make_float4(0,0,0,0); rw.f = make_float4(0,0,0,0); }
        }
#pragma unroll
        for (int kk = 0; kk < 8; kk++) {
            f4u a0, a1, b0, b1;
            a0.f = *(const float4*)&As[kk][ty * 8];
            a1.f = *(const float4*)&As[kk][ty * 8 + 4];
            b0.f = *(const float4*)&Ws[kk][tx * 8];
            b1.f = *(const float4*)&Ws[kk][tx * 8 + 4];
            ull bv[4] = {b0.u[0], b0.u[1], b1.u[0], b1.u[1]};
            float av[8] = {a0.s[0], a0.s[1], a0.s[2], a0.s[3],
                           a1.s[0], a1.s[1], a1.s[2], a1.s[3]};
#pragma unroll
            for (int i = 0; i < 8; i++) {
                ull ap = pack2(av[i], av[i]);
#pragma unroll
                for (int p = 0; p < 4; p++)
                    acc[i][p] = fma2(ap, bv[p], acc[i][p]);
            }
        }
        __syncthreads();
    }

    f4u bl0, bl1;
    bl0.f = *(const float4*)&bias[g0 + tx * 8];
    bl1.f = *(const float4*)&bias[g0 + tx * 8 + 4];

#pragma unroll
    for (int i = 0; i < 8; i++) {
        int m = m0 + ty * 8 + i;
        float* outp = g_xproj + ((size_t)dir * MN + m) * GN + g0 + tx * 8;
        f4u o0, o1;
#pragma unroll
        for (int p = 0; p < 2; p++) {
            uf2 v; v.u = acc[i][p];
            o0.s[2 * p]     = v.f.x + bl0.s[2 * p];
            o0.s[2 * p + 1] = v.f.y + bl0.s[2 * p + 1];
        }
#pragma unroll
        for (int p = 0; p < 2; p++) {
            uf2 v; v.u = acc[i][p + 2];
            o1.s[2 * p]     = v.f.x + bl1.s[2 * p];
            o1.s[2 * p + 1] = v.f.y + bl1.s[2 * p + 1];
        }
        *(float4*)&outp[0] = o0.f;
        *(float4*)&outp[4] = o1.f;
    }
}

// ---------------- GRU step: bf16-split tensor-core GEMM + fused pointwise ----------------
// Block tile: 32 j x 32 b x 3 gates. 8 warps; warp = 16 b x 8 j x 3 gates.
// hgates[b][g] = sum_k h[b][k] * W[g][k];  split x = hi+lo, D += Ah*Bh + Ah*Bl + Al*Bh.
#define SKC 32
#define SSTRIDE 40   // smem row stride in bf16 halves (80B, conflict-free ldmatrix)
__global__ __launch_bounds__(256) void step_kernel(const float* __restrict__ bhf,
                                                   const float* __restrict__ bhb,
                                                   const int*   __restrict__ slen,
                                                   int t) {
    __shared__ __align__(16) __nv_bfloat16 sAh[2][32 * SSTRIDE];
    __shared__ __align__(16) __nv_bfloat16 sAl[2][32 * SSTRIDE];
    __shared__ __align__(16) __nv_bfloat16 sBh[2][96 * SSTRIDE];
    __shared__ __align__(16) __nv_bfloat16 sBl[2][96 * SSTRIDE];

    int dir = blockIdx.z;
    int tt  = dir ? (TN - 1 - t) : t;
    const float* bh = dir ? bhb : bhf;
    int j0 = blockIdx.x * 32;
    int b0 = blockIdx.y * 32;
    int tid = threadIdx.x;
    int lane = tid & 31;
    int w = tid >> 5;
    int bw = w & 1;          // 0..1 : 16-row batch subtile
    int jw = w >> 1;         // 0..3 : 8-col j subtile
    int pp = t & 1;

    const float* hsrc = g_h + (size_t)(dir * 2 + pp) * BN * HN;
    float*       hdst = g_h + (size_t)(dir * 2 + (pp ^ 1)) * BN * HN;
    const __nv_bfloat16* hbh = g_hbh + (size_t)(dir * 2 + pp) * BN * HN;
    const __nv_bfloat16* hbl = g_hbl + (size_t)(dir * 2 + pp) * BN * HN;
    __nv_bfloat16* hbh_d = g_hbh + (size_t)(dir * 2 + (pp ^ 1)) * BN * HN;
    __nv_bfloat16* hbl_d = g_hbl + (size_t)(dir * 2 + (pp ^ 1)) * BN * HN;
    const __nv_bfloat16* Wh = g_Wbh + (size_t)dir * GN * HN;
    const __nv_bfloat16* Wl = g_Wbl + (size_t)dir * GN * HN;

    // ---- cp.async load mapping ----
    // A: 32 rows x 32 k halves (64B = 4 chunks). 128 chunks/array; tid<128 -> hi, else lo.
    int aSel = tid >> 7;
    int aRow = (tid & 127) >> 2;
    int aCh  = tid & 3;
    u32 aDst0 = smem_u32(&(aSel ? sAl : sAh)[0][aRow * SSTRIDE + aCh * 8]);
    const __nv_bfloat16* aSrc = (aSel ? hbl : hbh) + (size_t)(b0 + aRow) * HN + aCh * 8;
    // B: 96 rows x 4 chunks = 384 per array, 768 total => 3 per thread.
    u32 bDst0[3];
    const __nv_bfloat16* bSrc[3];
#pragma unroll
    for (int p = 0; p < 3; p++) {
        int idx = tid + 256 * p;         // 0..767
        int sel = idx >= 384;
        int q   = sel ? (idx - 384) : idx;
        int r   = q >> 2;                // 0..95  (gate*32 + jj)
        int ch  = q & 3;
        bDst0[p] = smem_u32(&(sel ? sBl : sBh)[0][r * SSTRIDE + ch * 8]);
        int wrow = (r >> 5) * HN + j0 + (r & 31);
        bSrc[p]  = (sel ? Wl : Wh) + (size_t)wrow * HN + ch * 8;
    }
    const u32 aBufBytes = 32 * SSTRIDE * 2;
    const u32 bBufBytes = 96 * SSTRIDE * 2;

    // ---- ldmatrix lane offsets (halves within buffer) ----
    int offA = (bw * 16 + (lane & 15)) * SSTRIDE + (lane >> 4) * 8;
    int offB = (jw * 8 + (lane & 7)) * SSTRIDE + ((lane >> 3) & 1) * 8;
    u32 baseAh = smem_u32(&sAh[0][0]), baseAl = smem_u32(&sAl[0][0]);
    u32 baseBh = smem_u32(&sBh[0][0]), baseBl = smem_u32(&sBl[0][0]);

    float d[3][4];
#pragma unroll
    for (int g = 0; g < 3; g++)
#pragma unroll
        for (int q = 0; q < 4; q++) d[g][q] = 0.0f;

    // prologue: stage 0
    cpa16(aDst0, aSrc);
#pragma unroll
    for (int p = 0; p < 3; p++) cpa16(bDst0[p], bSrc[p]);
    cpa_commit();

#pragma unroll 2
    for (int s = 0; s < HN / SKC; s++) {
        int buf = s & 1;
        cpa_wait0();
        __syncthreads();
        if (s + 1 < HN / SKC) {
            int nb = (s + 1) & 1;
            int k0 = (s + 1) * SKC;
            cpa16(aDst0 + nb * aBufBytes, aSrc + k0);
#pragma unroll
            for (int p = 0; p < 3; p++) cpa16(bDst0[p] + nb * bBufBytes, bSrc[p] + k0);
            cpa_commit();
        }
#pragma unroll
        for (int k16 = 0; k16 < 2; k16++) {
            u32 ah[4], al[4];
            ldsm4(baseAh + buf * aBufBytes + (offA + k16 * 16) * 2, ah[0], ah[1], ah[2], ah[3]);
            ldsm4(baseAl + buf * aBufBytes + (offA + k16 * 16) * 2, al[0], al[1], al[2], al[3]);
#pragma unroll
            for (int g = 0; g < 3; g++) {
                u32 bhr[2], blr[2];
                u32 boff = (offB + g * 32 * SSTRIDE + k16 * 16) * 2 + buf * bBufBytes;
                ldsm2(baseBh + boff, bhr[0], bhr[1]);
                ldsm2(baseBl + boff, blr[0], blr[1]);
                mma_bf16(d[g], ah, bhr);
                mma_bf16(d[g], ah, blr);
                mma_bf16(d[g], al, bhr);
            }
        }
        __syncthreads();
    }

    // ---- epilogue: GRU pointwise ----
    int r0 = lane >> 2;
    int c0 = (lane & 3) * 2;
    const float* xpb = g_xproj + ((size_t)dir * MN + (size_t)tt * BN) * GN;

#pragma unroll
    for (int half = 0; half < 2; half++) {
        int b = b0 + bw * 16 + r0 + half * 8;
        const float* xp = xpb + (size_t)b * GN;
        bool m = tt < slen[b];
#pragma unroll
        for (int cc = 0; cc < 2; cc++) {
            int j = j0 + jw * 8 + c0 + cc;
            int q = half * 2 + cc;
            float dR = d[0][q], dZ = d[1][q], dN = d[2][q];
            float r = sigf(xp[j]          + dR + bh[j]);
            float z = sigf(xp[HN + j]     + dZ + bh[HN + j]);
            float n = tanhfast(xp[2 * HN + j] + r * (dN + bh[2 * HN + j]));
            float hold = hsrc[(size_t)b * HN + j];
            float hv = (1.0f - z) * n + z * hold;
            float hout = m ? hv : hold;
            hdst[(size_t)b * HN + j] = hout;
            g_out[(((size_t)dir * TN + tt) * BN + b) * HN + j] = m ? hv : 0.0f;
            __nv_bfloat16 hi, lo;
            split_bf16(hout, hi, lo);
            hbh_d[(size_t)b * HN + j] = hi;
            hbl_d[(size_t)b * HN + j] = lo;
        }
    }
}

// ---------------- logits ----------------
__global__ void logits_kernel(const int* __restrict__ sidx) {
    int jb = blockIdx.x;
    int t  = blockIdx.y;
    int tid = threadIdx.x;    // 128

    const float* of = g_out + (((size_t)0 * TN + t) * BN + jb) * HN;
    const float* ob = g_out + (((size_t)1 * TN + t) * BN + jb) * HN;
    float s = 0.0f;
    for (int h = tid; h < HN; h += 128)
        s += of[h] * g_v[h] + ob[h] * g_v[HN + h];

    for (int o = 16; o > 0; o >>= 1) s += __shfl_down_sync(0xffffffff, s, o);
    __shared__ float red[4];
    if ((tid & 31) == 0) red[tid >> 5] = s;
    __syncthreads();
    if (tid == 0) {
        float tot = red[0] + red[1] + red[2] + red[3] + g_cbias;
        g_logits[(size_t)sidx[jb] * TN + t] = tot;
    }
}

// ---------------- softmax ----------------
__global__ void softmax_kernel(const int* __restrict__ seqlen) {
    int b = blockIdx.x;
    int tid = threadIdx.x;    // 256
    int len = seqlen[b];
    bool valid = (tid < TN) && (tid < len);
    float l = valid ? g_logits[(size_t)b * TN + tid] : -1e30f;

    __shared__ float sm[256];
    sm[tid] = l;
    __syncthreads();
    for (int s = 128; s > 0; s >>= 1) {
        if (tid < s) sm[tid] = fmaxf(sm[tid], sm[tid + s]);
        __syncthreads();
    }
    float mx = sm[0];
    __syncthreads();
    float e = valid ? expf(l - mx) : 0.0f;
    sm[tid] = e;
    __syncthreads();
    for (int s = 128; s > 0; s >>= 1) {
        if (tid < s) sm[tid] += sm[tid + s];
        __syncthreads();
    }
    float inv = 1.0f / sm[0];
    if (tid < TN) g_att[(size_t)b * TN + tid] = e * inv;
}

// ---------------- weighted sum ----------------
__global__ void wsum_kernel(float* __restrict__ out) {
    int ob  = blockIdx.x;
    int h   = blockIdx.y * 256 + threadIdx.x;
    int jb  = g_inv[ob];
    int d   = (h < HN) ? 0 : 1;
    int hh  = (h < HN) ? h : (h - HN);

    const float* av   = g_att + (size_t)ob * TN;
    const float* base = g_out + ((size_t)d * TN * BN + jb) * HN + hh;

    float acc = 0.0f;
    for (int t = 0; t < TN; t++)
        acc += av[t] * base[(size_t)t * BN * HN];
    out[(size_t)ob * (2 * HN) + h] = acc;
}

// ---------------- launch ----------------
extern "C" void kernel_launch(void* const* d_in, const int* in_sizes, int n_in,
                              void* d_out, int out_size) {
    const float* inp    = (const float*)d_in[0];
    const float* Wih_f  = (const float*)d_in[1];
    const float* Whh_f  = (const float*)d_in[2];
    const float* bih_f  = (const float*)d_in[3];
    const float* bhh_f  = (const float*)d_in[4];
    const float* Wih_b  = (const float*)d_in[5];
    const float* Whh_b  = (const float*)d_in[6];
    const float* bih_b  = (const float*)d_in[7];
    const float* bhh_b  = (const float*)d_in[8];
    const float* Wattn  = (const float*)d_in[9];
    const float* battn  = (const float*)d_in[10];
    const float* Wcomb  = (const float*)d_in[11];
    const int*   slen_s = (const int*)d_in[12];
    const int*   sidx   = (const int*)d_in[13];
    const int*   seqlen = (const int*)d_in[14];
    float* out = (float*)d_out;

    init_kernel<<<(2 * 2 * BN * HN + 255) / 256, 256>>>();
    convw_kernel<<<(2 * GN * HN + 255) / 256, 256>>>(Whh_f, Whh_b);
    prep_kernel<<<1, 1024>>>(Wattn, battn, Wcomb, sidx);
    proj_kernel<<<dim3(MN / 128, GN / 128, 2), 256>>>(inp, Wih_f, bih_f, Wih_b, bih_b);
    for (int t = 0; t < TN; t++)
        step_kernel<<<dim3(HN / 32, BN / 32, 2), 256>>>(bhh_f, bhh_b, slen_s, t);
    logits_kernel<<<dim3(BN, TN), 128>>>(sidx);
    softmax_kernel<<<BN, 256>>>(seqlen);
    wsum_kernel<<<dim3(BN, 4), 256>>>(out);
}

// round 4
// speedup vs baseline: 2.3155x; 1.3737x over previous
#include <cuda_runtime.h>
#include <cuda_bf16.h>
#include <math.h>

#define TN 200
#define BN 256
#define EN 300
#define HN 512
#define GN 1536            // 3*H
#define MN (TN*BN)         // 51200

typedef unsigned long long ull;
typedef unsigned int u32;

// ---------------- static device scratch ----------------
__device__ __align__(128) float g_xproj[(size_t)2 * TN * BN * GN];   // [dir][t*B+b][3H]
__device__ __align__(128) float g_out  [(size_t)2 * TN * BN * HN];   // [dir][t][b][H]
__device__ __align__(128) __nv_bfloat16 g_hbh[2 * 2 * BN * HN];      // h bf16 hi [dir][pp][b][k]
__device__ __align__(128) __nv_bfloat16 g_hbl[2 * 2 * BN * HN];      // h bf16 lo
__device__ int   g_bar[8];                                           // per (dir,bt) barrier
__device__ float g_v    [2 * HN];
__device__ float g_cbias;
__device__ int   g_inv  [BN];
__device__ float g_logits[BN * TN];
__device__ float g_att   [BN * TN];

// ---------------- helpers ----------------
__device__ __forceinline__ ull fma2(ull a, ull b, ull c) {
    ull d;
    asm("fma.rn.f32x2 %0, %1, %2, %3;" : "=l"(d) : "l"(a), "l"(b), "l"(c));
    return d;
}
__device__ __forceinline__ ull pack2(float x, float y) {
    ull d;
    asm("mov.b64 %0, {%1, %2};" : "=l"(d) : "f"(x), "f"(y));
    return d;
}
union f4u { float4 f; ull u[2]; float s[4]; };
union uf2 { ull u; float2 f; };

__device__ __forceinline__ float sigf(float x) { return 1.0f / (1.0f + __expf(-x)); }
__device__ __forceinline__ float tanhfast(float x) {
    float e = __expf(2.0f * x);
    return (e - 1.0f) / (e + 1.0f);
}
__device__ __forceinline__ u32 smem_u32(const void* p) {
    return (u32)__cvta_generic_to_shared(p);
}
__device__ __forceinline__ void cpa16(u32 s, const void* g) {
    asm volatile("cp.async.cg.shared.global [%0], [%1], 16;" :: "r"(s), "l"(g));
}
__device__ __forceinline__ void cpa_commit() { asm volatile("cp.async.commit_group;"); }
__device__ __forceinline__ void cpa_wait0()  { asm volatile("cp.async.wait_group 0;"); }

__device__ __forceinline__ void ldsm4(u32 addr, u32& r0, u32& r1, u32& r2, u32& r3) {
    asm volatile("ldmatrix.sync.aligned.m8n8.x4.shared.b16 {%0,%1,%2,%3}, [%4];"
                 : "=r"(r0), "=r"(r1), "=r"(r2), "=r"(r3) : "r"(addr));
}
__device__ __forceinline__ void mma_bf16(float* d, const u32* a, const u32* b) {
    asm volatile("mma.sync.aligned.m16n8k16.row.col.f32.bf16.bf16.f32 "
                 "{%0,%1,%2,%3}, {%4,%5,%6,%7}, {%8,%9}, {%0,%1,%2,%3};"
                 : "+f"(d[0]), "+f"(d[1]), "+f"(d[2]), "+f"(d[3])
                 : "r"(a[0]), "r"(a[1]), "r"(a[2]), "r"(a[3]), "r"(b[0]), "r"(b[1]));
}
__device__ __forceinline__ void split_bf16(float x, __nv_bfloat16& hi, __nv_bfloat16& lo) {
    hi = __float2bfloat16(x);
    lo = __float2bfloat16(x - __bfloat162float(hi));
}

// ---------------- init ----------------
__global__ void init_kernel() {
    int i = blockIdx.x * blockDim.x + threadIdx.x;
    if (i < 2 * 2 * BN * HN) {
        g_hbh[i] = __float2bfloat16(0.0f);
        g_hbl[i] = __float2bfloat16(0.0f);
    }
    if (i < 8) g_bar[i] = 0;
}

// ---------------- prep ----------------
__global__ void prep_kernel(const float* __restrict__ Wattn,
                            const float* __restrict__ battn,
                            const float* __restrict__ Wcomb,
                            const int*   __restrict__ sidx) {
    int tid = threadIdx.x;   // 1024
    float s = 0.0f;
    for (int m = 0; m < 2 * HN; m++)
        s += Wcomb[m] * Wattn[(size_t)m * (2 * HN) + tid];
    g_v[tid] = s;
    if (tid == 0) {
        float c = 0.0f;
        for (int m = 0; m < 2 * HN; m++) c += Wcomb[m] * battn[m];
        g_cbias = c;
    }
    if (tid < BN) g_inv[sidx[tid]] = tid;
}

// ---------------- input projection GEMM (f32x2) ----------------
__global__ __launch_bounds__(256) void proj_kernel(const float* __restrict__ inp,
                                                   const float* __restrict__ Wf,
                                                   const float* __restrict__ bf,
                                                   const float* __restrict__ Wb,
                                                   const float* __restrict__ bb) {
    __shared__ __align__(16) float As[8][128];
    __shared__ __align__(16) float Ws[8][128];

    int dir = blockIdx.z;
    const float* W    = dir ? Wb : Wf;
    const float* bias = dir ? bb : bf;
    int m0 = blockIdx.x * 128;
    int g0 = blockIdx.y * 128;
    int tid = threadIdx.x;
    int tx = tid & 15, ty = tid >> 4;
    int lr = tid >> 1, lk = (tid & 1) * 4;

    ull acc[8][4];
#pragma unroll
    for (int i = 0; i < 8; i++)
#pragma unroll
        for (int p = 0; p < 4; p++) acc[i][p] = 0ULL;

    const float* Arow = inp + (size_t)(m0 + lr) * EN;
    const float* Wrow = W   + (size_t)(g0 + lr) * EN;

    const int NCH = (EN + 7) / 8;   // 38
    f4u ra, rw;
    {
        int k = lk;
        if (k + 3 < EN) { ra.f = *(const float4*)&Arow[k]; rw.f = *(const float4*)&Wrow[k]; }
        else { ra.f = make_float4(0,0,0,0); rw.f = make_float4(0,0,0,0); }
    }

    for (int c = 0; c < NCH; c++) {
#pragma unroll
        for (int u = 0; u < 4; u++) {
            As[lk + u][lr] = ra.s[u];
            Ws[lk + u][lr] = rw.s[u];
        }
        __syncthreads();
        if (c + 1 < NCH) {
            int k = (c + 1) * 8 + lk;
            if (k + 3 < EN) { ra.f = *(const float4*)&Arow[k]; rw.f = *(const float4*)&Wrow[k]; }
            else { ra.f = make_float4(0,0,0,0); rw.f = make_float4(0,0,0,0); }
        }
#pragma unroll
        for (int kk = 0; kk < 8; kk++) {
            f4u a0, a1, b0, b1;
            a0.f = *(const float4*)&As[kk][ty * 8];
            a1.f = *(const float4*)&As[kk][ty * 8 + 4];
            b0.f = *(const float4*)&Ws[kk][tx * 8];
            b1.f = *(const float4*)&Ws[kk][tx * 8 + 4];
            ull bv[4] = {b0.u[0], b0.u[1], b1.u[0], b1.u[1]};
            float av[8] = {a0.s[0], a0.s[1], a0.s[2], a0.s[3],
                           a1.s[0], a1.s[1], a1.s[2], a1.s[3]};
#pragma unroll
            for (int i = 0; i < 8; i++) {
                ull ap = pack2(av[i], av[i]);
#pragma unroll
                for (int p = 0; p < 4; p++)
                    acc[i][p] = fma2(ap, bv[p], acc[i][p]);
            }
        }
        __syncthreads();
    }

    f4u bl0, bl1;
    bl0.f = *(const float4*)&bias[g0 + tx * 8];
    bl1.f = *(const float4*)&bias[g0 + tx * 8 + 4];

#pragma unroll
    for (int i = 0; i < 8; i++) {
        int m = m0 + ty * 8 + i;
        float* outp = g_xproj + ((size_t)dir * MN + m) * GN + g0 + tx * 8;
        f4u o0, o1;
#pragma unroll
        for (int p = 0; p < 2; p++) {
            uf2 v; v.u = acc[i][p];
            o0.s[2 * p]     = v.f.x + bl0.s[2 * p];
            o0.s[2 * p + 1] = v.f.y + bl0.s[2 * p + 1];
        }
#pragma unroll
        for (int p = 0; p < 2; p++) {
            uf2 v; v.u = acc[i][p + 2];
            o1.s[2 * p]     = v.f.x + bl1.s[2 * p];
            o1.s[2 * p + 1] = v.f.y + bl1.s[2 * p + 1];
        }
        *(float4*)&outp[0] = o0.f;
        *(float4*)&outp[4] = o1.f;
    }
}

// ---------------- persistent GRU kernel: all 200 steps ----------------
// 128 blocks = 16 jt x 4 bt x 2 dir. Block: 32 j x 3 gates x 64 b, K=512.
// Weights resident in smem (bf16 hi/lo). h exchanged via global bf16 hi/lo.
// Per-group (dir,bt) 16-block atomic barrier between steps.
#define WST 520                   // weight smem row stride (halves)
#define AST 40                    // A stage row stride (halves)
#define WBYTES (96 * WST * 2)     // 99840 per array
#define AARR   (64 * AST * 2)     // 5120: one (buf,arr) plane
#define ABUF   (2 * AARR)         // 10240: one buf (hi+lo)
#define SMEM_TOTAL (2 * WBYTES + 2 * ABUF)   // 220160

__global__ __launch_bounds__(256, 1) void persist_kernel(
    const float* __restrict__ Whf, const float* __restrict__ Whb,
    const float* __restrict__ bhf, const float* __restrict__ bhb,
    const int*   __restrict__ slen)
{
    extern __shared__ __align__(16) char smem[];
    __nv_bfloat16* sWh = (__nv_bfloat16*)smem;
    __nv_bfloat16* sWl = sWh + 96 * WST;
    __nv_bfloat16* sA  = (__nv_bfloat16*)(smem + 2 * WBYTES);

    int jt = blockIdx.x, bt = blockIdx.y, dir = blockIdx.z;
    int j0 = jt * 32, b0 = bt * 64;
    int tid = threadIdx.x, lane = tid & 31, w = tid >> 5;
    int wr = w & 3;        // warp row: 16 b each
    int c  = w >> 2;       // warp col: 48 gate-cols each
    int ql = lane & 3, rl = lane >> 2;
    const float* W  = dir ? Whb : Whf;
    const float* bh = dir ? bhb : bhf;
    int grp = dir * 4 + bt;

    // ---- fill resident weights: physical row p = c*48 + (jgrp*3+g)*8 + s ----
    for (int i = tid; i < 96 * 128; i += 256) {
        int rw_ = i >> 7;             // g*32 + jj
        int g = rw_ >> 5, jj = rw_ & 31;
        int k4 = (i & 127) * 4;
        float4 v = *(const float4*)&W[(size_t)(g * HN + j0 + jj) * HN + k4];
        int p = (jj >> 4) * 48 + (((jj >> 3) & 1) * 3 + g) * 8 + (jj & 7);
        const float* vs = (const float*)&v;
#pragma unroll
        for (int u = 0; u < 4; u++) {
            __nv_bfloat16 hi, lo;
            split_bf16(vs[u], hi, lo);
            sWh[p * WST + k4 + u] = hi;
            sWl[p * WST + k4 + u] = lo;
        }
    }
    __syncthreads();

    // ---- per-thread constants ----
    int jbase = j0 + c * 16 + ql * 2;        // j for jgrp 0 (add jgrp*8)
    float2 biasv[3][2];
#pragma unroll
    for (int g = 0; g < 3; g++)
#pragma unroll
        for (int jg = 0; jg < 2; jg++)
            biasv[g][jg] = *(const float2*)&bh[g * HN + jbase + jg * 8];
    int sl0 = slen[b0 + wr * 16 + rl];
    int sl1 = slen[b0 + wr * 16 + rl + 8];

    float hold[2][2][2];                      // [half][jgrp][cc]
#pragma unroll
    for (int a = 0; a < 2; a++)
#pragma unroll
        for (int b = 0; b < 2; b++)
#pragma unroll
            for (int d2 = 0; d2 < 2; d2++) hold[a][b][d2] = 0.0f;

    // cp.async mapping: 512 16B chunks / 256 threads = 2 each
    int arrSel[2], aRow[2], aCh[2];
    size_t aOffG[2];
    u32 aOffS[2];
#pragma unroll
    for (int p = 0; p < 2; p++) {
        int idx = tid + 256 * p;              // 0..511
        arrSel[p] = idx >> 8;                 // 0 hi, 1 lo
        aRow[p] = (idx & 255) >> 2;
        aCh[p]  = idx & 3;
        aOffG[p] = (size_t)(b0 + aRow[p]) * HN + aCh[p] * 8;
        aOffS[p] = smem_u32(sA) + (u32)(((arrSel[p] * 64 + aRow[p]) * AST + aCh[p] * 8) * 2);
    }

    // ldsm bases
    u32 aBaseH = smem_u32(sA) + (u32)(((wr * 16 + (lane & 15)) * AST + (lane >> 4) * 8) * 2);
    u32 aBaseL = aBaseH + AARR;
    int rowB = c * 48 + (lane & 7) + ((lane >> 4) << 3);
    u32 bBaseH[3], bBaseL[3];
#pragma unroll
    for (int p = 0; p < 3; p++) {
        u32 off = (u32)(((rowB + p * 16) * WST + ((lane >> 3) & 1) * 8) * 2);
        bBaseH[p] = smem_u32(sWh) + off;
        bBaseL[p] = smem_u32(sWl) + off;
    }

    // ---- time loop ----
    for (int t = 0; t < TN; t++) {
        int pp = t & 1;
        int tt = dir ? (TN - 1 - t) : t;

        if (t) {
            if (tid == 0) {
                int target = 16 * t;
                while (*((volatile int*)&g_bar[grp]) < target) __nanosleep(64);
                __threadfence();
            }
            __syncthreads();
        }

        const __nv_bfloat16* hbp = g_hbh + (size_t)(dir * 2 + pp) * BN * HN;
        const __nv_bfloat16* hlp = g_hbl + (size_t)(dir * 2 + pp) * BN * HN;
        __nv_bfloat16* hbd = g_hbh + (size_t)(dir * 2 + (pp ^ 1)) * BN * HN;
        __nv_bfloat16* hld = g_hbl + (size_t)(dir * 2 + (pp ^ 1)) * BN * HN;
        const __nv_bfloat16* aSrc0 = (arrSel[0] ? hlp : hbp) + aOffG[0];
        const __nv_bfloat16* aSrc1 = (arrSel[1] ? hlp : hbp) + aOffG[1];

        // prefetch xproj for this step
        float2 xpre[2][2][3];
        const float* xb = g_xproj + ((size_t)dir * MN + (size_t)tt * BN) * GN;
#pragma unroll
        for (int h2 = 0; h2 < 2; h2++) {
            int b = b0 + wr * 16 + rl + h2 * 8;
            const float* xr = xb + (size_t)b * GN;
#pragma unroll
            for (int jg = 0; jg < 2; jg++)
#pragma unroll
                for (int g = 0; g < 3; g++)
                    xpre[h2][jg][g] = *(const float2*)&xr[g * HN + jbase + jg * 8];
        }

        float d[6][4];
#pragma unroll
        for (int n = 0; n < 6; n++)
#pragma unroll
            for (int q = 0; q < 4; q++) d[n][q] = 0.0f;

        // stage chunk 0
        cpa16(aOffS[0], aSrc0);
        cpa16(aOffS[1], aSrc1);
        cpa_commit();

        for (int chunk = 0; chunk < 16; chunk++) {
            int buf = chunk & 1;
            cpa_wait0();
            __syncthreads();
            if (chunk < 15) {
                int nb = buf ^ 1;
                cpa16(aOffS[0] + nb * ABUF, aSrc0 + (chunk + 1) * 32);
                cpa16(aOffS[1] + nb * ABUF, aSrc1 + (chunk + 1) * 32);
                cpa_commit();
            }
#pragma unroll
            for (int k16 = 0; k16 < 2; k16++) {
                int kk = chunk * 2 + k16;
                u32 abo = buf * ABUF + k16 * 32;
                u32 ah[4], al[4];
                ldsm4(aBaseH + abo, ah[0], ah[1], ah[2], ah[3]);
                ldsm4(aBaseL + abo, al[0], al[1], al[2], al[3]);
                u32 kb = kk * 32;
#pragma unroll
                for (int p = 0; p < 3; p++) {
                    u32 bhv[4], blv[4];
                    ldsm4(bBaseH[p] + kb, bhv[0], bhv[1], bhv[2], bhv[3]);
                    ldsm4(bBaseL[p] + kb, blv[0], blv[1], blv[2], blv[3]);
                    mma_bf16(d[2 * p],     ah, &bhv[0]);
                    mma_bf16(d[2 * p],     ah, &blv[0]);
                    mma_bf16(d[2 * p],     al, &bhv[0]);
                    mma_bf16(d[2 * p + 1], ah, &bhv[2]);
                    mma_bf16(d[2 * p + 1], ah, &blv[2]);
                    mma_bf16(d[2 * p + 1], al, &bhv[2]);
                }
            }
            __syncthreads();
        }

        // ---- epilogue ----
#pragma unroll
        for (int h2 = 0; h2 < 2; h2++) {
            int b = b0 + wr * 16 + rl + h2 * 8;
            bool m = tt < (h2 ? sl1 : sl0);
#pragma unroll
            for (int jg = 0; jg < 2; jg++) {
                int j = jbase + jg * 8;
                float ho[2], oo[2];
#pragma unroll
                for (int cc = 0; cc < 2; cc++) {
                    int q = h2 * 2 + cc;
                    const float* xR = (const float*)&xpre[h2][jg][0];
                    const float* xZ = (const float*)&xpre[h2][jg][1];
                    const float* xN = (const float*)&xpre[h2][jg][2];
                    const float* bR = (const float*)&biasv[0][jg];
                    const float* bZ = (const float*)&biasv[1][jg];
                    const float* bNp = (const float*)&biasv[2][jg];
                    float r = sigf(xR[cc] + d[jg * 3 + 0][q] + bR[cc]);
                    float z = sigf(xZ[cc] + d[jg * 3 + 1][q] + bZ[cc]);
                    float n = tanhfast(xN[cc] + r * (d[jg * 3 + 2][q] + bNp[cc]));
                    float hprev = hold[h2][jg][cc];
                    float hv = (1.0f - z) * n + z * hprev;
                    float hout = m ? hv : hprev;
                    hold[h2][jg][cc] = hout;
                    ho[cc] = hout;
                    oo[cc] = m ? hv : 0.0f;
                }
                *(float2*)&g_out[(((size_t)dir * TN + tt) * BN + b) * HN + j] =
                    make_float2(oo[0], oo[1]);
                __nv_bfloat16 hi0, lo0, hi1, lo1;
                split_bf16(ho[0], hi0, lo0);
                split_bf16(ho[1], hi1, lo1);
                __nv_bfloat162 hp; hp.x = hi0; hp.y = hi1;
                __nv_bfloat162 lp; lp.x = lo0; lp.y = lo1;
                *(__nv_bfloat162*)&hbd[(size_t)b * HN + j] = hp;
                *(__nv_bfloat162*)&hld[(size_t)b * HN + j] = lp;
            }
        }

        __threadfence();
        __syncthreads();
        if (tid == 0) atomicAdd(&g_bar[grp], 1);
    }
}

// ---------------- logits ----------------
__global__ void logits_kernel(const int* __restrict__ sidx) {
    int jb = blockIdx.x;
    int t  = blockIdx.y;
    int tid = threadIdx.x;    // 128

    const float* of = g_out + (((size_t)0 * TN + t) * BN + jb) * HN;
    const float* ob = g_out + (((size_t)1 * TN + t) * BN + jb) * HN;
    float s = 0.0f;
    for (int h = tid; h < HN; h += 128)
        s += of[h] * g_v[h] + ob[h] * g_v[HN + h];

    for (int o = 16; o > 0; o >>= 1) s += __shfl_down_sync(0xffffffff, s, o);
    __shared__ float red[4];
    if ((tid & 31) == 0) red[tid >> 5] = s;
    __syncthreads();
    if (tid == 0) {
        float tot = red[0] + red[1] + red[2] + red[3] + g_cbias;
        g_logits[(size_t)sidx[jb] * TN + t] = tot;
    }
}

// ---------------- softmax ----------------
__global__ void softmax_kernel(const int* __restrict__ seqlen) {
    int b = blockIdx.x;
    int tid = threadIdx.x;    // 256
    int len = seqlen[b];
    bool valid = (tid < TN) && (tid < len);
    float l = valid ? g_logits[(size_t)b * TN + tid] : -1e30f;

    __shared__ float sm[256];
    sm[tid] = l;
    __syncthreads();
    for (int s = 128; s > 0; s >>= 1) {
        if (tid < s) sm[tid] = fmaxf(sm[tid], sm[tid + s]);
        __syncthreads();
    }
    float mx = sm[0];
    __syncthreads();
    float e = valid ? expf(l - mx) : 0.0f;
    sm[tid] = e;
    __syncthreads();
    for (int s = 128; s > 0; s >>= 1) {
        if (tid < s) sm[tid] += sm[tid + s];
        __syncthreads();
    }
    float inv = 1.0f / sm[0];
    if (tid < TN) g_att[(size_t)b * TN + tid] = e * inv;
}

// ---------------- weighted sum ----------------
__global__ void wsum_kernel(float* __restrict__ out) {
    int ob  = blockIdx.x;
    int h   = blockIdx.y * 256 + threadIdx.x;
    int jb  = g_inv[ob];
    int d   = (h < HN) ? 0 : 1;
    int hh  = (h < HN) ? h : (h - HN);

    const float* av   = g_att + (size_t)ob * TN;
    const float* base = g_out + ((size_t)d * TN * BN + jb) * HN + hh;

    float acc = 0.0f;
    for (int t = 0; t < TN; t++)
        acc += av[t] * base[(size_t)t * BN * HN];
    out[(size_t)ob * (2 * HN) + h] = acc;
}

// ---------------- launch ----------------
extern "C" void kernel_launch(void* const* d_in, const int* in_sizes, int n_in,
                              void* d_out, int out_size) {
    const float* inp    = (const float*)d_in[0];
    const float* Wih_f  = (const float*)d_in[1];
    const float* Whh_f  = (const float*)d_in[2];
    const float* bih_f  = (const float*)d_in[3];
    const float* bhh_f  = (const float*)d_in[4];
    const float* Wih_b  = (const float*)d_in[5];
    const float* Whh_b  = (const float*)d_in[6];
    const float* bih_b  = (const float*)d_in[7];
    const float* bhh_b  = (const float*)d_in[8];
    const float* Wattn  = (const float*)d_in[9];
    const float* battn  = (const float*)d_in[10];
    const float* Wcomb  = (const float*)d_in[11];
    const int*   slen_s = (const int*)d_in[12];
    const int*   sidx   = (const int*)d_in[13];
    const int*   seqlen = (const int*)d_in[14];
    float* out = (float*)d_out;

    cudaFuncSetAttribute(persist_kernel,
                         cudaFuncAttributeMaxDynamicSharedMemorySize, SMEM_TOTAL);

    init_kernel<<<(2 * 2 * BN * HN + 255) / 256, 256>>>();
    prep_kernel<<<1, 1024>>>(Wattn, battn, Wcomb, sidx);
    proj_kernel<<<dim3(MN / 128, GN / 128, 2), 256>>>(inp, Wih_f, bih_f, Wih_b, bih_b);
    persist_kernel<<<dim3(16, 4, 2), 256, SMEM_TOTAL>>>(Whh_f, Whh_b, bhh_f, bhh_b, slen_s);
    logits_kernel<<<dim3(BN, TN), 128>>>(sidx);
    softmax_kernel<<<BN, 256>>>(seqlen);
    wsum_kernel<<<dim3(BN, 4), 256>>>(out);
}

// round 5
// speedup vs baseline: 3.5751x; 1.5440x over previous
#include <cuda_runtime.h>
#include <cuda_bf16.h>
#include <math.h>

#define TN 200
#define BN 256
#define EN 300
#define HN 512
#define GN 1536            // 3*H
#define MN (TN*BN)         // 51200
#define KP 320             // padded K for input projection

typedef unsigned long long ull;
typedef unsigned int u32;

// ---------------- static device scratch ----------------
__device__ __align__(128) float g_xproj[(size_t)2 * TN * BN * GN];   // [dir][t*B+b][3H]
__device__ __align__(128) float g_out  [(size_t)2 * TN * BN * HN];   // [dir][t][b][H]
__device__ __align__(128) __nv_bfloat16 g_hbh[2 * 2 * BN * HN];      // h bf16 hi
__device__ __align__(128) __nv_bfloat16 g_hbl[2 * 2 * BN * HN];      // h bf16 lo
__device__ __align__(128) __nv_bfloat16 g_ibh[(size_t)MN * KP];      // inp bf16 hi (padded)
__device__ __align__(128) __nv_bfloat16 g_ibl[(size_t)MN * KP];      // inp bf16 lo
__device__ __align__(128) __nv_bfloat16 g_wbh[2 * GN * KP];          // W_ih bf16 hi
__device__ __align__(128) __nv_bfloat16 g_wbl[2 * GN * KP];          // W_ih bf16 lo
__device__ int   g_bar[8];
__device__ float g_v    [2 * HN];
__device__ int   g_inv  [BN];
__device__ float g_logits[BN * TN];
__device__ float g_att   [BN * TN];

// ---------------- helpers ----------------
__device__ __forceinline__ float sigf(float x) { return 1.0f / (1.0f + __expf(-x)); }
__device__ __forceinline__ float tanhfast(float x) {
    float e = __expf(2.0f * x);
    return (e - 1.0f) / (e + 1.0f);
}
__device__ __forceinline__ u32 smem_u32(const void* p) {
    return (u32)__cvta_generic_to_shared(p);
}
__device__ __forceinline__ void cpa16(u32 s, const void* g) {
    asm volatile("cp.async.cg.shared.global [%0], [%1], 16;" :: "r"(s), "l"(g));
}
__device__ __forceinline__ void cpa_commit() { asm volatile("cp.async.commit_group;"); }
__device__ __forceinline__ void cpa_wait0()  { asm volatile("cp.async.wait_group 0;"); }
__device__ __forceinline__ void cpa_wait1()  { asm volatile("cp.async.wait_group 1;"); }

__device__ __forceinline__ void ldsm4(u32 addr, u32& r0, u32& r1, u32& r2, u32& r3) {
    asm volatile("ldmatrix.sync.aligned.m8n8.x4.shared.b16 {%0,%1,%2,%3}, [%4];"
                 : "=r"(r0), "=r"(r1), "=r"(r2), "=r"(r3) : "r"(addr));
}
__device__ __forceinline__ void mma_bf16(float* d, const u32* a, const u32* b) {
    asm volatile("mma.sync.aligned.m16n8k16.row.col.f32.bf16.bf16.f32 "
                 "{%0,%1,%2,%3}, {%4,%5,%6,%7}, {%8,%9}, {%0,%1,%2,%3};"
                 : "+f"(d[0]), "+f"(d[1]), "+f"(d[2]), "+f"(d[3])
                 : "r"(a[0]), "r"(a[1]), "r"(a[2]), "r"(a[3]), "r"(b[0]), "r"(b[1]));
}
__device__ __forceinline__ void split_bf16(float x, __nv_bfloat16& hi, __nv_bfloat16& lo) {
    hi = __float2bfloat16(x);
    lo = __float2bfloat16(x - __bfloat162float(hi));
}

// ---------------- init ----------------
__global__ void init_kernel() {
    int i = blockIdx.x * blockDim.x + threadIdx.x;
    if (i < 2 * 2 * BN * HN) {
        g_hbh[i] = __float2bfloat16(0.0f);
        g_hbl[i] = __float2bfloat16(0.0f);
    }
    if (i < BN * TN) g_logits[i] = 0.0f;
    if (i < 8) g_bar[i] = 0;
}

// ---------------- prep: v = W_comb @ W_attn, inverse perm ----------------
__global__ void prep_kernel(const float* __restrict__ Wattn,
                            const float* __restrict__ Wcomb,
                            const int*   __restrict__ sidx) {
    int tid = threadIdx.x;   // 1024
    float s = 0.0f;
    for (int m = 0; m < 2 * HN; m++)
        s += Wcomb[m] * Wattn[(size_t)m * (2 * HN) + tid];
    g_v[tid] = s;
    if (tid < BN) g_inv[sidx[tid]] = tid;
}

// ---------------- convert inp to bf16 hi/lo (padded K) ----------------
__global__ void convi_kernel(const float* __restrict__ inp) {
    size_t i = (size_t)blockIdx.x * blockDim.x + threadIdx.x;
    if (i < (size_t)MN * KP) {
        int m = (int)(i / KP), k = (int)(i % KP);
        float x = (k < EN) ? inp[(size_t)m * EN + k] : 0.0f;
        __nv_bfloat16 hi, lo;
        split_bf16(x, hi, lo);
        g_ibh[i] = hi; g_ibl[i] = lo;
    }
}

// ---------------- convert W_ih to bf16 hi/lo (padded K) ----------------
__global__ void convw_kernel(const float* __restrict__ Wf,
                             const float* __restrict__ Wb) {
    int i = blockIdx.x * blockDim.x + threadIdx.x;
    if (i < 2 * GN * KP) {
        int d = i / (GN * KP);
        int r = (i / KP) % GN;
        int k = i % KP;
        const float* W = d ? Wb : Wf;
        float x = (k < EN) ? W[(size_t)r * EN + k] : 0.0f;
        __nv_bfloat16 hi, lo;
        split_bf16(x, hi, lo);
        g_wbh[i] = hi; g_wbl[i] = lo;
    }
}

// ---------------- input projection: bf16-split tensor-core GEMM ----------------
// Block 128m x 96n, K=320 (10 chunks of 32). 8 warps: wr=w&3 (32 m), c=w>>2 (48 n).
#define PAARR (128*40*2)      // 10240 B: one A array (hi or lo) per stage
#define PBARR (96*40*2)       // 7680
#define PABUF (2*PAARR)       // 20480
#define PBBUF (2*PBARR)       // 15360
#define PSTAGE (PABUF+PBBUF)  // 35840
#define PSMEM (2*PSTAGE)      // 71680

__global__ __launch_bounds__(256) void proj_mma(const float* __restrict__ bf_,
                                                const float* __restrict__ bb_) {
    extern __shared__ __align__(16) char ps[];
    u32 smb = smem_u32(ps);
    int dir = blockIdx.z;
    int m0 = blockIdx.x * 128;
    int n0 = blockIdx.y * 96;
    const float* bias = dir ? bb_ : bf_;
    int tid = threadIdx.x, lane = tid & 31, w = tid >> 5;
    int wr = w & 3, c = w >> 2;
    int ql = lane & 3, rl = lane >> 2;

    const __nv_bfloat16* Wh = g_wbh + (size_t)dir * GN * KP;
    const __nv_bfloat16* Wl = g_wbl + (size_t)dir * GN * KP;

    u32 aDst[4]; const __nv_bfloat16* aSrc[4];
#pragma unroll
    for (int p = 0; p < 4; p++) {
        int idx = tid + 256 * p;          // 0..1023
        int sel = idx >> 9, q = idx & 511, r = q >> 2, ch = q & 3;
        aDst[p] = smb + sel * PAARR + (u32)((r * 40 + ch * 8) * 2);
        aSrc[p] = (sel ? g_ibl : g_ibh) + (size_t)(m0 + r) * KP + ch * 8;
    }
    u32 bDst[3]; const __nv_bfloat16* bSrc[3];
#pragma unroll
    for (int p = 0; p < 3; p++) {
        int idx = tid + 256 * p;          // 0..767
        int sel = idx >= 384;
        int q = sel ? idx - 384 : idx;
        int r = q >> 2, ch = q & 3;
        bDst[p] = smb + PABUF + sel * PBARR + (u32)((r * 40 + ch * 8) * 2);
        bSrc[p] = (sel ? Wl : Wh) + (size_t)(n0 + r) * KP + ch * 8;
    }

    u32 aB[2][2];
#pragma unroll
    for (int mf = 0; mf < 2; mf++) {
        u32 off = (u32)(((wr * 32 + mf * 16 + (lane & 15)) * 40 + (lane >> 4) * 8) * 2);
        aB[mf][0] = smb + off; aB[mf][1] = smb + PAARR + off;
    }
    int rowB = c * 48 + (lane & 7) + ((lane >> 4) << 3);
    u32 bB[3][2];
#pragma unroll
    for (int p = 0; p < 3; p++) {
        u32 off = PABUF + (u32)(((rowB + p * 16) * 40 + ((lane >> 3) & 1) * 8) * 2);
        bB[p][0] = smb + off; bB[p][1] = smb + PBARR + off;
    }

    float d[2][6][4];
#pragma unroll
    for (int mf = 0; mf < 2; mf++)
#pragma unroll
        for (int n = 0; n < 6; n++)
#pragma unroll
            for (int q = 0; q < 4; q++) d[mf][n][q] = 0.0f;

#pragma unroll
    for (int p = 0; p < 4; p++) cpa16(aDst[p], aSrc[p]);
#pragma unroll
    for (int p = 0; p < 3; p++) cpa16(bDst[p], bSrc[p]);
    cpa_commit();

    for (int ck = 0; ck < 10; ck++) {
        int st = ck & 1;
        cpa_wait0();
        __syncthreads();
        if (ck + 1 < 10) {
            int ns = (ck + 1) & 1;
#pragma unroll
            for (int p = 0; p < 4; p++) cpa16(aDst[p] + ns * PSTAGE, aSrc[p] + (ck + 1) * 32);
#pragma unroll
            for (int p = 0; p < 3; p++) cpa16(bDst[p] + ns * PSTAGE, bSrc[p] + (ck + 1) * 32);
            cpa_commit();
        }
#pragma unroll
        for (int k16 = 0; k16 < 2; k16++) {
            u32 ko = st * PSTAGE + k16 * 32;
            u32 bhv[3][4], blv[3][4];
#pragma unroll
            for (int p = 0; p < 3; p++) {
                ldsm4(bB[p][0] + ko, bhv[p][0], bhv[p][1], bhv[p][2], bhv[p][3]);
                ldsm4(bB[p][1] + ko, blv[p][0], blv[p][1], blv[p][2], blv[p][3]);
            }
#pragma unroll
            for (int mf = 0; mf < 2; mf++) {
                u32 ah[4], al[4];
                ldsm4(aB[mf][0] + ko, ah[0], ah[1], ah[2], ah[3]);
                ldsm4(aB[mf][1] + ko, al[0], al[1], al[2], al[3]);
#pragma unroll
                for (int p = 0; p < 3; p++) {
                    mma_bf16(d[mf][2 * p],     ah, &bhv[p][0]);
                    mma_bf16(d[mf][2 * p],     ah, &blv[p][0]);
                    mma_bf16(d[mf][2 * p],     al, &bhv[p][0]);
                    mma_bf16(d[mf][2 * p + 1], ah, &bhv[p][2]);
                    mma_bf16(d[mf][2 * p + 1], ah, &blv[p][2]);
                    mma_bf16(d[mf][2 * p + 1], al, &bhv[p][2]);
                }
            }
        }
    }

    // epilogue
#pragma unroll
    for (int nfr = 0; nfr < 6; nfr++) {
        int n = n0 + c * 48 + nfr * 8 + ql * 2;
        float2 b2 = *(const float2*)&bias[n];
#pragma unroll
        for (int mf = 0; mf < 2; mf++) {
            int m = m0 + wr * 32 + mf * 16 + rl;
            float* o0 = &g_xproj[((size_t)dir * MN + m) * GN + n];
            float* o1 = &g_xproj[((size_t)dir * MN + m + 8) * GN + n];
            *(float2*)o0 = make_float2(d[mf][nfr][0] + b2.x, d[mf][nfr][1] + b2.y);
            *(float2*)o1 = make_float2(d[mf][nfr][2] + b2.x, d[mf][nfr][3] + b2.y);
        }
    }
}

// ---------------- persistent GRU kernel ----------------
// 128 blocks = 16 jt x 4 bt x 2 dir. Weights resident in smem. 3-stage cp.async.
// Group runs only Lg = slen[b0] steps (lengths sorted descending). Logits fused.
#define WST 520
#define AST 40
#define WBYTES (96 * WST * 2)       // 99840
#define AARR   (64 * AST * 2)       // 5120
#define ABUF   (2 * AARR)           // 10240 per stage
#define SMEM_TOTAL (2 * WBYTES + 3 * ABUF + 64 * 4)   // 230656

__global__ __launch_bounds__(256, 1) void persist_kernel(
    const float* __restrict__ Whf, const float* __restrict__ Whb,
    const float* __restrict__ bhf, const float* __restrict__ bhb,
    const int*   __restrict__ slen, const int* __restrict__ sidx)
{
    extern __shared__ __align__(16) char smem[];
    __nv_bfloat16* sWh = (__nv_bfloat16*)smem;
    __nv_bfloat16* sWl = sWh + 96 * WST;
    __nv_bfloat16* sA  = (__nv_bfloat16*)(smem + 2 * WBYTES);
    float* slog = (float*)(smem + 2 * WBYTES + 3 * ABUF);

    int jt = blockIdx.x, bt = blockIdx.y, dir = blockIdx.z;
    int j0 = jt * 32, b0 = bt * 64;
    int tid = threadIdx.x, lane = tid & 31, w = tid >> 5;
    int wr = w & 3;
    int c  = w >> 2;
    int ql = lane & 3, rl = lane >> 2;
    const float* W  = dir ? Whb : Whf;
    const float* bh = dir ? bhb : bhf;
    int grp = dir * 4 + bt;
    int Lg = slen[b0];                       // group max length (sorted desc)

    // ---- resident weights ----
    for (int i = tid; i < 96 * 128; i += 256) {
        int rw_ = i >> 7;
        int g = rw_ >> 5, jj = rw_ & 31;
        int k4 = (i & 127) * 4;
        float4 v = *(const float4*)&W[(size_t)(g * HN + j0 + jj) * HN + k4];
        int p = (jj >> 4) * 48 + (((jj >> 3) & 1) * 3 + g) * 8 + (jj & 7);
        const float* vs = (const float*)&v;
#pragma unroll
        for (int u = 0; u < 4; u++) {
            __nv_bfloat16 hi, lo;
            split_bf16(vs[u], hi, lo);
            sWh[p * WST + k4 + u] = hi;
            sWl[p * WST + k4 + u] = lo;
        }
    }
    if (tid < 64) slog[tid] = 0.0f;
    __syncthreads();

    // ---- per-thread constants ----
    int jbase = j0 + c * 16 + ql * 2;
    float2 biasv[3][2];
#pragma unroll
    for (int g = 0; g < 3; g++)
#pragma unroll
        for (int jg = 0; jg < 2; jg++)
            biasv[g][jg] = *(const float2*)&bh[g * HN + jbase + jg * 8];
    float2 vv[2];
#pragma unroll
    for (int jg = 0; jg < 2; jg++)
        vv[jg] = *(const float2*)&g_v[dir * HN + jbase + jg * 8];
    int sl0 = slen[b0 + wr * 16 + rl];
    int sl1 = slen[b0 + wr * 16 + rl + 8];
    int sob = (tid < 64) ? sidx[b0 + tid] : 0;

    float hold[2][2][2];
#pragma unroll
    for (int a = 0; a < 2; a++)
#pragma unroll
        for (int b = 0; b < 2; b++)
#pragma unroll
            for (int d2 = 0; d2 < 2; d2++) hold[a][b][d2] = 0.0f;

    // cp.async mapping: 512 16B chunks / 256 threads = 2 each
    int arrSel[2];
    size_t aOffG[2];
    u32 aOffS[2];
#pragma unroll
    for (int p = 0; p < 2; p++) {
        int idx = tid + 256 * p;
        arrSel[p] = idx >> 8;
        int r = (idx & 255) >> 2;
        int ch = idx & 3;
        aOffG[p] = (size_t)(b0 + r) * HN + ch * 8;
        aOffS[p] = smem_u32(sA) + (u32)(((arrSel[p] * 64 + r) * AST + ch * 8) * 2);
    }

    u32 aBaseH = smem_u32(sA) + (u32)(((wr * 16 + (lane & 15)) * AST + (lane >> 4) * 8) * 2);
    u32 aBaseL = aBaseH + AARR;
    int rowB = c * 48 + (lane & 7) + ((lane >> 4) << 3);
    u32 bBaseH[3], bBaseL[3];
#pragma unroll
    for (int p = 0; p < 3; p++) {
        u32 off = (u32)(((rowB + p * 16) * WST + ((lane >> 3) & 1) * 8) * 2);
        bBaseH[p] = smem_u32(sWh) + off;
        bBaseL[p] = smem_u32(sWl) + off;
    }

    // ---- time loop (only Lg steps) ----
    for (int i = 0; i < Lg; i++) {
        int pp = i & 1;
        int tt = dir ? (Lg - 1 - i) : i;

        // xproj prefetch (independent of barrier)
        float2 xpre[2][2][3];
        const float* xb = g_xproj + ((size_t)dir * MN + (size_t)tt * BN) * GN;
#pragma unroll
        for (int h2 = 0; h2 < 2; h2++) {
            int b = b0 + wr * 16 + rl + h2 * 8;
            const float* xr = xb + (size_t)b * GN;
#pragma unroll
            for (int jg = 0; jg < 2; jg++)
#pragma unroll
                for (int g = 0; g < 3; g++)
                    xpre[h2][jg][g] = *(const float2*)&xr[g * HN + jbase + jg * 8];
        }

        if (i) {
            if (tid == 0) {
                int target = 16 * i;
                while (*((volatile int*)&g_bar[grp]) < target) __nanosleep(64);
                __threadfence();
            }
            __syncthreads();
        }

        const __nv_bfloat16* hbp = g_hbh + (size_t)(dir * 2 + pp) * BN * HN;
        const __nv_bfloat16* hlp = g_hbl + (size_t)(dir * 2 + pp) * BN * HN;
        __nv_bfloat16* hbd = g_hbh + (size_t)(dir * 2 + (pp ^ 1)) * BN * HN;
        __nv_bfloat16* hld = g_hbl + (size_t)(dir * 2 + (pp ^ 1)) * BN * HN;
        const __nv_bfloat16* aSrc0 = (arrSel[0] ? hlp : hbp) + aOffG[0];
        const __nv_bfloat16* aSrc1 = (arrSel[1] ? hlp : hbp) + aOffG[1];

        float d[6][4];
#pragma unroll
        for (int n = 0; n < 6; n++)
#pragma unroll
            for (int q = 0; q < 4; q++) d[n][q] = 0.0f;

        // 3-stage pipeline prologue
        cpa16(aOffS[0], aSrc0);
        cpa16(aOffS[1], aSrc1);
        cpa_commit();
        cpa16(aOffS[0] + ABUF, aSrc0 + 32);
        cpa16(aOffS[1] + ABUF, aSrc1 + 32);
        cpa_commit();

        for (int ck = 0; ck < 16; ck++) {
            if (ck < 15) cpa_wait1(); else cpa_wait0();
            __syncthreads();
            if (ck + 2 < 16) {
                int ns = (ck + 2) % 3;
                cpa16(aOffS[0] + ns * ABUF, aSrc0 + (ck + 2) * 32);
                cpa16(aOffS[1] + ns * ABUF, aSrc1 + (ck + 2) * 32);
                cpa_commit();
            }
            int st = ck % 3;
#pragma unroll
            for (int k16 = 0; k16 < 2; k16++) {
                int kk = ck * 2 + k16;
                u32 abo = st * ABUF + k16 * 32;
                u32 ah[4], al[4];
                ldsm4(aBaseH + abo, ah[0], ah[1], ah[2], ah[3]);
                ldsm4(aBaseL + abo, al[0], al[1], al[2], al[3]);
                u32 kb = kk * 32;
#pragma unroll
                for (int p = 0; p < 3; p++) {
                    u32 bhv[4], blv[4];
                    ldsm4(bBaseH[p] + kb, bhv[0], bhv[1], bhv[2], bhv[3]);
                    ldsm4(bBaseL[p] + kb, blv[0], blv[1], blv[2], blv[3]);
                    mma_bf16(d[2 * p],     ah, &bhv[0]);
                    mma_bf16(d[2 * p],     ah, &blv[0]);
                    mma_bf16(d[2 * p],     al, &bhv[0]);
                    mma_bf16(d[2 * p + 1], ah, &bhv[2]);
                    mma_bf16(d[2 * p + 1], ah, &blv[2]);
                    mma_bf16(d[2 * p + 1], al, &bhv[2]);
                }
            }
        }

        // ---- epilogue: GRU pointwise + fused logits partial ----
        float lp[2] = {0.0f, 0.0f};
#pragma unroll
        for (int h2 = 0; h2 < 2; h2++) {
            int b = b0 + wr * 16 + rl + h2 * 8;
            bool m = tt < (h2 ? sl1 : sl0);
#pragma unroll
            for (int jg = 0; jg < 2; jg++) {
                int j = jbase + jg * 8;
                float ho[2], oo[2];
#pragma unroll
                for (int cc = 0; cc < 2; cc++) {
                    int q = h2 * 2 + cc;
                    const float* xR = (const float*)&xpre[h2][jg][0];
                    const float* xZ = (const float*)&xpre[h2][jg][1];
                    const float* xN = (const float*)&xpre[h2][jg][2];
                    const float* bR = (const float*)&biasv[0][jg];
                    const float* bZ = (const float*)&biasv[1][jg];
                    const float* bNp = (const float*)&biasv[2][jg];
                    float r = sigf(xR[cc] + d[jg * 3 + 0][q] + bR[cc]);
                    float z = sigf(xZ[cc] + d[jg * 3 + 1][q] + bZ[cc]);
                    float n = tanhfast(xN[cc] + r * (d[jg * 3 + 2][q] + bNp[cc]));
                    float hprev = hold[h2][jg][cc];
                    float hv = (1.0f - z) * n + z * hprev;
                    float hout = m ? hv : hprev;
                    hold[h2][jg][cc] = hout;
                    ho[cc] = hout;
                    oo[cc] = m ? hv : 0.0f;
                }
                lp[h2] += oo[0] * ((const float*)&vv[jg])[0] + oo[1] * ((const float*)&vv[jg])[1];
                *(float2*)&g_out[(((size_t)dir * TN + tt) * BN + b) * HN + j] =
                    make_float2(oo[0], oo[1]);
                __nv_bfloat16 hi0, lo0, hi1, lo1;
                split_bf16(ho[0], hi0, lo0);
                split_bf16(ho[1], hi1, lo1);
                __nv_bfloat162 hp; hp.x = hi0; hp.y = hi1;
                __nv_bfloat162 lq; lq.x = lo0; lq.y = lo1;
                *(__nv_bfloat162*)&hbd[(size_t)b * HN + j] = hp;
                *(__nv_bfloat162*)&hld[(size_t)b * HN + j] = lq;
            }
        }
        // reduce logits partial over ql lanes (bits 0-1), then shared accumulate
#pragma unroll
        for (int h2 = 0; h2 < 2; h2++) {
            lp[h2] += __shfl_xor_sync(0xffffffff, lp[h2], 1);
            lp[h2] += __shfl_xor_sync(0xffffffff, lp[h2], 2);
            if (ql == 0) atomicAdd(&slog[wr * 16 + rl + h2 * 8], lp[h2]);
        }

        __threadfence();
        __syncthreads();
        if (tid < 64) {
            float s = slog[tid];
            slog[tid] = 0.0f;
            if (s != 0.0f) atomicAdd(&g_logits[(size_t)sob * TN + tt], s);
        }
        if (tid == 0) atomicAdd(&g_bar[grp], 1);
    }
}

// ---------------- softmax ----------------
__global__ void softmax_kernel(const int* __restrict__ seqlen) {
    int b = blockIdx.x;
    int tid = threadIdx.x;    // 256
    int len = seqlen[b];
    bool valid = (tid < TN) && (tid < len);
    float l = valid ? g_logits[(size_t)b * TN + tid] : -1e30f;

    __shared__ float sm[256];
    sm[tid] = l;
    __syncthreads();
    for (int s = 128; s > 0; s >>= 1) {
        if (tid < s) sm[tid] = fmaxf(sm[tid], sm[tid + s]);
        __syncthreads();
    }
    float mx = sm[0];
    __syncthreads();
    float e = valid ? expf(l - mx) : 0.0f;
    sm[tid] = e;
    __syncthreads();
    for (int s = 128; s > 0; s >>= 1) {
        if (tid < s) sm[tid] += sm[tid + s];
        __syncthreads();
    }
    float inv = 1.0f / sm[0];
    if (tid < TN) g_att[(size_t)b * TN + tid] = e * inv;
}

// ---------------- weighted sum ----------------
__global__ void wsum_kernel(float* __restrict__ out) {
    int ob  = blockIdx.x;
    int h   = blockIdx.y * 256 + threadIdx.x;
    int jb  = g_inv[ob];
    int d   = (h < HN) ? 0 : 1;
    int hh  = (h < HN) ? h : (h - HN);

    const float* av   = g_att + (size_t)ob * TN;
    const float* base = g_out + ((size_t)d * TN * BN + jb) * HN + hh;

    float acc = 0.0f;
    for (int t = 0; t < TN; t++)
        acc += av[t] * base[(size_t)t * BN * HN];
    out[(size_t)ob * (2 * HN) + h] = acc;
}

// ---------------- launch ----------------
extern "C" void kernel_launch(void* const* d_in, const int* in_sizes, int n_in,
                              void* d_out, int out_size) {
    const float* inp    = (const float*)d_in[0];
    const float* Wih_f  = (const float*)d_in[1];
    const float* Whh_f  = (const float*)d_in[2];
    const float* bih_f  = (const float*)d_in[3];
    const float* bhh_f  = (const float*)d_in[4];
    const float* Wih_b  = (const float*)d_in[5];
    const float* Whh_b  = (const float*)d_in[6];
    const float* bih_b  = (const float*)d_in[7];
    const float* bhh_b  = (const float*)d_in[8];
    const float* Wattn  = (const float*)d_in[9];
    const float* Wcomb  = (const float*)d_in[11];
    const int*   slen_s = (const int*)d_in[12];
    const int*   sidx   = (const int*)d_in[13];
    const int*   seqlen = (const int*)d_in[14];
    float* out = (float*)d_out;

    cudaFuncSetAttribute(persist_kernel,
                         cudaFuncAttributeMaxDynamicSharedMemorySize, SMEM_TOTAL);
    cudaFuncSetAttribute(proj_mma,
                         cudaFuncAttributeMaxDynamicSharedMemorySize, PSMEM);

    init_kernel<<<(2 * 2 * BN * HN + 255) / 256, 256>>>();
    prep_kernel<<<1, 1024>>>(Wattn, Wcomb, sidx);
    convi_kernel<<<(int)(((size_t)MN * KP + 255) / 256), 256>>>(inp);
    convw_kernel<<<(2 * GN * KP + 255) / 256, 256>>>(Wih_f, Wih_b);
    proj_mma<<<dim3(MN / 128, GN / 96, 2), 256, PSMEM>>>(bih_f, bih_b);
    persist_kernel<<<dim3(16, 4, 2), 256, SMEM_TOTAL>>>(Whh_f, Whh_b, bhh_f, bhh_b,
                                                        slen_s, sidx);
    softmax_kernel<<<BN, 256>>>(seqlen);
    wsum_kernel<<<dim3(BN, 4), 256>>>(out);
}

// round 6
// speedup vs baseline: 3.7226x; 1.0413x over previous
#include <cuda_runtime.h>
#include <cuda_bf16.h>
#include <math.h>

#define TN 200
#define BN 256
#define EN 300
#define HN 512
#define GN 1536            // 3*H
#define MN (TN*BN)         // 51200
#define KP 320             // padded K for input projection

typedef unsigned long long ull;
typedef unsigned int u32;

// ---------------- static device scratch ----------------
__device__ __align__(128) float g_xproj[(size_t)2 * TN * BN * GN];   // [dir][t*B+b][3H]
__device__ __align__(128) float g_out  [(size_t)2 * TN * BN * HN];   // [dir][t][b][H]
__device__ __align__(128) __nv_bfloat16 g_hbh[2 * 2 * BN * HN];      // h bf16 hi
__device__ __align__(128) __nv_bfloat16 g_hbl[2 * 2 * BN * HN];      // h bf16 lo
__device__ __align__(128) __nv_bfloat16 g_ibh[(size_t)MN * KP];      // inp bf16 hi (padded)
__device__ __align__(128) __nv_bfloat16 g_ibl[(size_t)MN * KP];      // inp bf16 lo
__device__ __align__(128) __nv_bfloat16 g_wbh[2 * GN * KP];          // W_ih bf16 hi
__device__ __align__(128) __nv_bfloat16 g_wbl[2 * GN * KP];          // W_ih bf16 lo
__device__ u32   g_bar[8];
__device__ float g_v    [2 * HN];
__device__ int   g_inv  [BN];
__device__ float g_logits[BN * TN];

// ---------------- helpers ----------------
__device__ __forceinline__ float sigf(float x) { return 1.0f / (1.0f + __expf(-x)); }
__device__ __forceinline__ float tanhfast(float x) {
    float e = __expf(2.0f * x);
    return (e - 1.0f) / (e + 1.0f);
}
__device__ __forceinline__ u32 smem_u32(const void* p) {
    return (u32)__cvta_generic_to_shared(p);
}
__device__ __forceinline__ void cpa16(u32 s, const void* g) {
    asm volatile("cp.async.cg.shared.global [%0], [%1], 16;" :: "r"(s), "l"(g));
}
__device__ __forceinline__ void cpa_commit() { asm volatile("cp.async.commit_group;"); }
__device__ __forceinline__ void cpa_wait0()  { asm volatile("cp.async.wait_group 0;"); }
__device__ __forceinline__ void cpa_wait1()  { asm volatile("cp.async.wait_group 1;"); }

__device__ __forceinline__ void ldsm4(u32 addr, u32& r0, u32& r1, u32& r2, u32& r3) {
    asm volatile("ldmatrix.sync.aligned.m8n8.x4.shared.b16 {%0,%1,%2,%3}, [%4];"
                 : "=r"(r0), "=r"(r1), "=r"(r2), "=r"(r3) : "r"(addr));
}
__device__ __forceinline__ void mma_bf16(float* d, const u32* a, const u32* b) {
    asm volatile("mma.sync.aligned.m16n8k16.row.col.f32.bf16.bf16.f32 "
                 "{%0,%1,%2,%3}, {%4,%5,%6,%7}, {%8,%9}, {%0,%1,%2,%3};"
                 : "+f"(d[0]), "+f"(d[1]), "+f"(d[2]), "+f"(d[3])
                 : "r"(a[0]), "r"(a[1]), "r"(a[2]), "r"(a[3]), "r"(b[0]), "r"(b[1]));
}
__device__ __forceinline__ void split_bf16(float x, __nv_bfloat16& hi, __nv_bfloat16& lo) {
    hi = __float2bfloat16(x);
    lo = __float2bfloat16(x - __bfloat162float(hi));
}
__device__ __forceinline__ void bar_arrive(u32* p) {
    asm volatile("red.release.gpu.global.add.u32 [%0], %1;" :: "l"(p), "r"(1u) : "memory");
}
__device__ __forceinline__ u32 bar_peek(u32* p) {
    u32 v;
    asm volatile("ld.acquire.gpu.global.u32 %0, [%1];" : "=r"(v) : "l"(p) : "memory");
    return v;
}

// ---------------- init ----------------
__global__ void init_kernel() {
    int i = blockIdx.x * blockDim.x + threadIdx.x;
    if (i < 2 * 2 * BN * HN) {
        g_hbh[i] = __float2bfloat16(0.0f);
        g_hbl[i] = __float2bfloat16(0.0f);
    }
    if (i < BN * TN) g_logits[i] = 0.0f;
    if (i < 8) g_bar[i] = 0u;
}

// ---------------- prep: v = W_comb @ W_attn, inverse perm ----------------
__global__ void prep_kernel(const float* __restrict__ Wattn,
                            const float* __restrict__ Wcomb,
                            const int*   __restrict__ sidx) {
    int tid = threadIdx.x;   // 1024
    float s = 0.0f;
    for (int m = 0; m < 2 * HN; m++)
        s += Wcomb[m] * Wattn[(size_t)m * (2 * HN) + tid];
    g_v[tid] = s;
    if (tid < BN) g_inv[sidx[tid]] = tid;
}

// ---------------- convert inp to bf16 hi/lo (padded K) ----------------
__global__ void convi_kernel(const float* __restrict__ inp) {
    size_t i = (size_t)blockIdx.x * blockDim.x + threadIdx.x;
    if (i < (size_t)MN * KP) {
        int m = (int)(i / KP), k = (int)(i % KP);
        float x = (k < EN) ? inp[(size_t)m * EN + k] : 0.0f;
        __nv_bfloat16 hi, lo;
        split_bf16(x, hi, lo);
        g_ibh[i] = hi; g_ibl[i] = lo;
    }
}

// ---------------- convert W_ih to bf16 hi/lo (padded K) ----------------
__global__ void convw_kernel(const float* __restrict__ Wf,
                             const float* __restrict__ Wb) {
    int i = blockIdx.x * blockDim.x + threadIdx.x;
    if (i < 2 * GN * KP) {
        int d = i / (GN * KP);
        int r = (i / KP) % GN;
        int k = i % KP;
        const float* W = d ? Wb : Wf;
        float x = (k < EN) ? W[(size_t)r * EN + k] : 0.0f;
        __nv_bfloat16 hi, lo;
        split_bf16(x, hi, lo);
        g_wbh[i] = hi; g_wbl[i] = lo;
    }
}

// ---------------- input projection: bf16-split tensor-core GEMM ----------------
#define PAARR (128*40*2)
#define PBARR (96*40*2)
#define PABUF (2*PAARR)
#define PBBUF (2*PBARR)
#define PSTAGE (PABUF+PBBUF)
#define PSMEM (2*PSTAGE)

__global__ __launch_bounds__(256) void proj_mma(const float* __restrict__ bf_,
                                                const float* __restrict__ bb_) {
    extern __shared__ __align__(16) char ps[];
    u32 smb = smem_u32(ps);
    int dir = blockIdx.z;
    int m0 = blockIdx.x * 128;
    int n0 = blockIdx.y * 96;
    const float* bias = dir ? bb_ : bf_;
    int tid = threadIdx.x, lane = tid & 31, w = tid >> 5;
    int wr = w & 3, c = w >> 2;
    int ql = lane & 3, rl = lane >> 2;

    const __nv_bfloat16* Wh = g_wbh + (size_t)dir * GN * KP;
    const __nv_bfloat16* Wl = g_wbl + (size_t)dir * GN * KP;

    u32 aDst[4]; const __nv_bfloat16* aSrc[4];
#pragma unroll
    for (int p = 0; p < 4; p++) {
        int idx = tid + 256 * p;
        int sel = idx >> 9, q = idx & 511, r = q >> 2, ch = q & 3;
        aDst[p] = smb + sel * PAARR + (u32)((r * 40 + ch * 8) * 2);
        aSrc[p] = (sel ? g_ibl : g_ibh) + (size_t)(m0 + r) * KP + ch * 8;
    }
    u32 bDst[3]; const __nv_bfloat16* bSrc[3];
#pragma unroll
    for (int p = 0; p < 3; p++) {
        int idx = tid + 256 * p;
        int sel = idx >= 384;
        int q = sel ? idx - 384 : idx;
        int r = q >> 2, ch = q & 3;
        bDst[p] = smb + PABUF + sel * PBARR + (u32)((r * 40 + ch * 8) * 2);
        bSrc[p] = (sel ? Wl : Wh) + (size_t)(n0 + r) * KP + ch * 8;
    }

    u32 aB[2][2];
#pragma unroll
    for (int mf = 0; mf < 2; mf++) {
        u32 off = (u32)(((wr * 32 + mf * 16 + (lane & 15)) * 40 + (lane >> 4) * 8) * 2);
        aB[mf][0] = smb + off; aB[mf][1] = smb + PAARR + off;
    }
    int rowB = c * 48 + (lane & 7) + ((lane >> 4) << 3);
    u32 bB[3][2];
#pragma unroll
    for (int p = 0; p < 3; p++) {
        u32 off = PABUF + (u32)(((rowB + p * 16) * 40 + ((lane >> 3) & 1) * 8) * 2);
        bB[p][0] = smb + off; bB[p][1] = smb + PBARR + off;
    }

    float d[2][6][4];
#pragma unroll
    for (int mf = 0; mf < 2; mf++)
#pragma unroll
        for (int n = 0; n < 6; n++)
#pragma unroll
            for (int q = 0; q < 4; q++) d[mf][n][q] = 0.0f;

#pragma unroll
    for (int p = 0; p < 4; p++) cpa16(aDst[p], aSrc[p]);
#pragma unroll
    for (int p = 0; p < 3; p++) cpa16(bDst[p], bSrc[p]);
    cpa_commit();

    for (int ck = 0; ck < 10; ck++) {
        int st = ck & 1;
        cpa_wait0();
        __syncthreads();
        if (ck + 1 < 10) {
            int ns = (ck + 1) & 1;
#pragma unroll
            for (int p = 0; p < 4; p++) cpa16(aDst[p] + ns * PSTAGE, aSrc[p] + (ck + 1) * 32);
#pragma unroll
            for (int p = 0; p < 3; p++) cpa16(bDst[p] + ns * PSTAGE, bSrc[p] + (ck + 1) * 32);
            cpa_commit();
        }
#pragma unroll
        for (int k16 = 0; k16 < 2; k16++) {
            u32 ko = st * PSTAGE + k16 * 32;
            u32 bhv[3][4], blv[3][4];
#pragma unroll
            for (int p = 0; p < 3; p++) {
                ldsm4(bB[p][0] + ko, bhv[p][0], bhv[p][1], bhv[p][2], bhv[p][3]);
                ldsm4(bB[p][1] + ko, blv[p][0], blv[p][1], blv[p][2], blv[p][3]);
            }
#pragma unroll
            for (int mf = 0; mf < 2; mf++) {
                u32 ah[4], al[4];
                ldsm4(aB[mf][0] + ko, ah[0], ah[1], ah[2], ah[3]);
                ldsm4(aB[mf][1] + ko, al[0], al[1], al[2], al[3]);
#pragma unroll
                for (int p = 0; p < 3; p++) {
                    mma_bf16(d[mf][2 * p],     ah, &bhv[p][0]);
                    mma_bf16(d[mf][2 * p],     ah, &blv[p][0]);
                    mma_bf16(d[mf][2 * p],     al, &bhv[p][0]);
                    mma_bf16(d[mf][2 * p + 1], ah, &bhv[p][2]);
                    mma_bf16(d[mf][2 * p + 1], ah, &blv[p][2]);
                    mma_bf16(d[mf][2 * p + 1], al, &bhv[p][2]);
                }
            }
        }
    }

#pragma unroll
    for (int nfr = 0; nfr < 6; nfr++) {
        int n = n0 + c * 48 + nfr * 8 + ql * 2;
        float2 b2 = *(const float2*)&bias[n];
#pragma unroll
        for (int mf = 0; mf < 2; mf++) {
            int m = m0 + wr * 32 + mf * 16 + rl;
            float* o0 = &g_xproj[((size_t)dir * MN + m) * GN + n];
            float* o1 = &g_xproj[((size_t)dir * MN + m + 8) * GN + n];
            *(float2*)o0 = make_float2(d[mf][nfr][0] + b2.x, d[mf][nfr][1] + b2.y);
            *(float2*)o1 = make_float2(d[mf][nfr][2] + b2.x, d[mf][nfr][3] + b2.y);
        }
    }
}

// ---------------- persistent GRU kernel ----------------
#define WST 520
#define AST 40
#define WBYTES (96 * WST * 2)       // 99840
#define AARR   (64 * AST * 2)       // 5120
#define ABUF   (2 * AARR)           // 10240 per stage
#define SMEM_TOTAL (2 * WBYTES + 3 * ABUF + 64 * 4)   // 230656

__global__ __launch_bounds__(256, 1) void persist_kernel(
    const float* __restrict__ Whf, const float* __restrict__ Whb,
    const float* __restrict__ bhf, const float* __restrict__ bhb,
    const int*   __restrict__ slen, const int* __restrict__ sidx)
{
    extern __shared__ __align__(16) char smem[];
    __nv_bfloat16* sWh = (__nv_bfloat16*)smem;
    __nv_bfloat16* sWl = sWh + 96 * WST;
    __nv_bfloat16* sA  = (__nv_bfloat16*)(smem + 2 * WBYTES);
    float* slog = (float*)(smem + 2 * WBYTES + 3 * ABUF);

    int jt = blockIdx.x, bt = blockIdx.y, dir = blockIdx.z;
    int j0 = jt * 32, b0 = bt * 64;
    int tid = threadIdx.x, lane = tid & 31, w = tid >> 5;
    int wr = w & 3;
    int c  = w >> 2;
    int ql = lane & 3, rl = lane >> 2;
    const float* W  = dir ? Whb : Whf;
    const float* bh = dir ? bhb : bhf;
    int grp = dir * 4 + bt;
    int Lg = slen[b0];

    // ---- resident weights ----
    for (int i = tid; i < 96 * 128; i += 256) {
        int rw_ = i >> 7;
        int g = rw_ >> 5, jj = rw_ & 31;
        int k4 = (i & 127) * 4;
        float4 v = *(const float4*)&W[(size_t)(g * HN + j0 + jj) * HN + k4];
        int p = (jj >> 4) * 48 + (((jj >> 3) & 1) * 3 + g) * 8 + (jj & 7);
        const float* vs = (const float*)&v;
#pragma unroll
        for (int u = 0; u < 4; u++) {
            __nv_bfloat16 hi, lo;
            split_bf16(vs[u], hi, lo);
            sWh[p * WST + k4 + u] = hi;
            sWl[p * WST + k4 + u] = lo;
        }
    }
    if (tid < 64) slog[tid] = 0.0f;
    __syncthreads();

    // ---- per-thread constants ----
    int jbase = j0 + c * 16 + ql * 2;
    float2 biasv[3][2];
#pragma unroll
    for (int g = 0; g < 3; g++)
#pragma unroll
        for (int jg = 0; jg < 2; jg++)
            biasv[g][jg] = *(const float2*)&bh[g * HN + jbase + jg * 8];
    float2 vv[2];
#pragma unroll
    for (int jg = 0; jg < 2; jg++)
        vv[jg] = *(const float2*)&g_v[dir * HN + jbase + jg * 8];
    int sl0 = slen[b0 + wr * 16 + rl];
    int sl1 = slen[b0 + wr * 16 + rl + 8];
    int sob = (tid < 64) ? sidx[b0 + tid] : 0;

    float hold[2][2][2];
#pragma unroll
    for (int a = 0; a < 2; a++)
#pragma unroll
        for (int b = 0; b < 2; b++)
#pragma unroll
            for (int d2 = 0; d2 < 2; d2++) hold[a][b][d2] = 0.0f;

    int arrSel[2];
    size_t aOffG[2];
    u32 aOffS[2];
#pragma unroll
    for (int p = 0; p < 2; p++) {
        int idx = tid + 256 * p;
        arrSel[p] = idx >> 8;
        int r = (idx & 255) >> 2;
        int ch = idx & 3;
        aOffG[p] = (size_t)(b0 + r) * HN + ch * 8;
        aOffS[p] = smem_u32(sA) + (u32)(((arrSel[p] * 64 + r) * AST + ch * 8) * 2);
    }

    u32 aBaseH = smem_u32(sA) + (u32)(((wr * 16 + (lane & 15)) * AST + (lane >> 4) * 8) * 2);
    u32 aBaseL = aBaseH + AARR;
    int rowB = c * 48 + (lane & 7) + ((lane >> 4) << 3);
    u32 bBaseH[3], bBaseL[3];
#pragma unroll
    for (int p = 0; p < 3; p++) {
        u32 off = (u32)(((rowB + p * 16) * WST + ((lane >> 3) & 1) * 8) * 2);
        bBaseH[p] = smem_u32(sWh) + off;
        bBaseL[p] = smem_u32(sWl) + off;
    }

    // ---- time loop ----
    for (int i = 0; i < Lg; i++) {
        int pp = i & 1;
        int tt = dir ? (Lg - 1 - i) : i;

        // xproj prefetch (overlaps barrier spin)
        float2 xpre[2][2][3];
        const float* xb = g_xproj + ((size_t)dir * MN + (size_t)tt * BN) * GN;
#pragma unroll
        for (int h2 = 0; h2 < 2; h2++) {
            int b = b0 + wr * 16 + rl + h2 * 8;
            const float* xr = xb + (size_t)b * GN;
#pragma unroll
            for (int jg = 0; jg < 2; jg++)
#pragma unroll
                for (int g = 0; g < 3; g++)
                    xpre[h2][jg][g] = *(const float2*)&xr[g * HN + jbase + jg * 8];
        }

        if (i) {
            if (tid == 0) {
                u32 target = 16u * (u32)i;
                while (bar_peek(&g_bar[grp]) < target) __nanosleep(32);
            }
            __syncthreads();
        }

        const __nv_bfloat16* hbp = g_hbh + (size_t)(dir * 2 + pp) * BN * HN;
        const __nv_bfloat16* hlp = g_hbl + (size_t)(dir * 2 + pp) * BN * HN;
        __nv_bfloat16* hbd = g_hbh + (size_t)(dir * 2 + (pp ^ 1)) * BN * HN;
        __nv_bfloat16* hld = g_hbl + (size_t)(dir * 2 + (pp ^ 1)) * BN * HN;
        const __nv_bfloat16* aSrc0 = (arrSel[0] ? hlp : hbp) + aOffG[0];
        const __nv_bfloat16* aSrc1 = (arrSel[1] ? hlp : hbp) + aOffG[1];

        float d[6][4];
#pragma unroll
        for (int n = 0; n < 6; n++)
#pragma unroll
            for (int q = 0; q < 4; q++) d[n][q] = 0.0f;

        cpa16(aOffS[0], aSrc0);
        cpa16(aOffS[1], aSrc1);
        cpa_commit();
        cpa16(aOffS[0] + ABUF, aSrc0 + 32);
        cpa16(aOffS[1] + ABUF, aSrc1 + 32);
        cpa_commit();

        for (int ck = 0; ck < 16; ck++) {
            if (ck < 15) cpa_wait1(); else cpa_wait0();
            __syncthreads();
            if (ck + 2 < 16) {
                int ns = (ck + 2) % 3;
                cpa16(aOffS[0] + ns * ABUF, aSrc0 + (ck + 2) * 32);
                cpa16(aOffS[1] + ns * ABUF, aSrc1 + (ck + 2) * 32);
                cpa_commit();
            }
            int st = ck % 3;
#pragma unroll
            for (int k16 = 0; k16 < 2; k16++) {
                int kk = ck * 2 + k16;
                u32 abo = st * ABUF + k16 * 32;
                u32 ah[4], al[4];
                ldsm4(aBaseH + abo, ah[0], ah[1], ah[2], ah[3]);
                ldsm4(aBaseL + abo, al[0], al[1], al[2], al[3]);
                u32 kb = kk * 32;
#pragma unroll
                for (int p = 0; p < 3; p++) {
                    u32 bhv[4], blv[4];
                    ldsm4(bBaseH[p] + kb, bhv[0], bhv[1], bhv[2], bhv[3]);
                    ldsm4(bBaseL[p] + kb, blv[0], blv[1], blv[2], blv[3]);
                    mma_bf16(d[2 * p],     ah, &bhv[0]);
                    mma_bf16(d[2 * p],     ah, &blv[0]);
                    mma_bf16(d[2 * p],     al, &bhv[0]);
                    mma_bf16(d[2 * p + 1], ah, &bhv[2]);
                    mma_bf16(d[2 * p + 1], ah, &blv[2]);
                    mma_bf16(d[2 * p + 1], al, &bhv[2]);
                }
            }
        }

        // ---- epilogue phase 1: compute h, store ONLY h (critical path) ----
        float oo[2][2][2];
#pragma unroll
        for (int h2 = 0; h2 < 2; h2++) {
            int b = b0 + wr * 16 + rl + h2 * 8;
            bool m = tt < (h2 ? sl1 : sl0);
#pragma unroll
            for (int jg = 0; jg < 2; jg++) {
                int j = jbase + jg * 8;
                float ho[2];
#pragma unroll
                for (int cc = 0; cc < 2; cc++) {
                    int q = h2 * 2 + cc;
                    const float* xR = (const float*)&xpre[h2][jg][0];
                    const float* xZ = (const float*)&xpre[h2][jg][1];
                    const float* xN = (const float*)&xpre[h2][jg][2];
                    const float* bR = (const float*)&biasv[0][jg];
                    const float* bZ = (const float*)&biasv[1][jg];
                    const float* bNp = (const float*)&biasv[2][jg];
                    float r = sigf(xR[cc] + d[jg * 3 + 0][q] + bR[cc]);
                    float z = sigf(xZ[cc] + d[jg * 3 + 1][q] + bZ[cc]);
                    float n = tanhfast(xN[cc] + r * (d[jg * 3 + 2][q] + bNp[cc]));
                    float hprev = hold[h2][jg][cc];
                    float hv = (1.0f - z) * n + z * hprev;
                    float hout = m ? hv : hprev;
                    hold[h2][jg][cc] = hout;
                    ho[cc] = hout;
                    oo[h2][jg][cc] = m ? hv : 0.0f;
                }
                __nv_bfloat16 hi0, lo0, hi1, lo1;
                split_bf16(ho[0], hi0, lo0);
                split_bf16(ho[1], hi1, lo1);
                __nv_bfloat162 hp; hp.x = hi0; hp.y = hi1;
                __nv_bfloat162 lq; lq.x = lo0; lq.y = lo1;
                *(__nv_bfloat162*)&hbd[(size_t)b * HN + j] = hp;
                *(__nv_bfloat162*)&hld[(size_t)b * HN + j] = lq;
            }
        }

        // ---- arrive: release-atomic (orders all CTA h-stores via syncthreads) ----
        __syncthreads();
        if (i + 1 < Lg && tid == 0) bar_arrive(&g_bar[grp]);

        // ---- epilogue phase 2 (off inter-block critical path): g_out + logits ----
        float lp[2] = {0.0f, 0.0f};
#pragma unroll
        for (int h2 = 0; h2 < 2; h2++) {
            int b = b0 + wr * 16 + rl + h2 * 8;
#pragma unroll
            for (int jg = 0; jg < 2; jg++) {
                int j = jbase + jg * 8;
                *(float2*)&g_out[(((size_t)dir * TN + tt) * BN + b) * HN + j] =
                    make_float2(oo[h2][jg][0], oo[h2][jg][1]);
                lp[h2] += oo[h2][jg][0] * ((const float*)&vv[jg])[0]
                        + oo[h2][jg][1] * ((const float*)&vv[jg])[1];
            }
        }
#pragma unroll
        for (int h2 = 0; h2 < 2; h2++) {
            lp[h2] += __shfl_xor_sync(0xffffffff, lp[h2], 1);
            lp[h2] += __shfl_xor_sync(0xffffffff, lp[h2], 2);
            if (ql == 0) atomicAdd(&slog[wr * 16 + rl + h2 * 8], lp[h2]);
        }
        __syncthreads();
        if (tid < 64) {
            float s = slog[tid];
            slog[tid] = 0.0f;
            if (s != 0.0f) atomicAdd(&g_logits[(size_t)sob * TN + tt], s);
        }
    }
}

// ---------------- fused softmax + weighted sum ----------------
__global__ __launch_bounds__(256) void attn_kernel(const int* __restrict__ seqlen,
                                                   float* __restrict__ out) {
    __shared__ float sa[256];
    __shared__ float red[256];
    int ob = blockIdx.x;
    int tid = threadIdx.x;
    int len = seqlen[ob];
    bool valid = (tid < TN) && (tid < len);
    float l = valid ? g_logits[(size_t)ob * TN + tid] : -1e30f;

    red[tid] = l;
    __syncthreads();
    for (int s = 128; s > 0; s >>= 1) {
        if (tid < s) red[tid] = fmaxf(red[tid], red[tid + s]);
        __syncthreads();
    }
    float mx = red[0];
    __syncthreads();
    float e = valid ? expf(l - mx) : 0.0f;
    red[tid] = e;
    __syncthreads();
    for (int s = 128; s > 0; s >>= 1) {
        if (tid < s) red[tid] += red[tid + s];
        __syncthreads();
    }
    sa[tid] = e / red[0];
    __syncthreads();

    int jb = g_inv[ob];
#pragma unroll
    for (int q = 0; q < 4; q++) {
        int h = q * 256 + tid;
        int d = (h >= HN);
        int hc = d ? h - HN : h;
        const float* base = g_out + ((size_t)d * TN * BN + jb) * HN + hc;
        float acc = 0.0f;
        for (int t = 0; t < len; t++)
            acc += sa[t] * base[(size_t)t * BN * HN];
        out[(size_t)ob * (2 * HN) + h] = acc;
    }
}

// ---------------- launch ----------------
extern "C" void kernel_launch(void* const* d_in, const int* in_sizes, int n_in,
                              void* d_out, int out_size) {
    const float* inp    = (const float*)d_in[0];
    const float* Wih_f  = (const float*)d_in[1];
    const float* Whh_f  = (const float*)d_in[2];
    const float* bih_f  = (const float*)d_in[3];
    const float* bhh_f  = (const float*)d_in[4];
    const float* Wih_b  = (const float*)d_in[5];
    const float* Whh_b  = (const float*)d_in[6];
    const float* bih_b  = (const float*)d_in[7];
    const float* bhh_b  = (const float*)d_in[8];
    const float* Wattn  = (const float*)d_in[9];
    const float* Wcomb  = (const float*)d_in[11];
    const int*   slen_s = (const int*)d_in[12];
    const int*   sidx   = (const int*)d_in[13];
    const int*   seqlen = (const int*)d_in[14];
    float* out = (float*)d_out;

    cudaFuncSetAttribute(persist_kernel,
                         cudaFuncAttributeMaxDynamicSharedMemorySize, SMEM_TOTAL);
    cudaFuncSetAttribute(proj_mma,
                         cudaFuncAttributeMaxDynamicSharedMemorySize, PSMEM);

    init_kernel<<<(2 * 2 * BN * HN + 255) / 256, 256>>>();
    prep_kernel<<<1, 1024>>>(Wattn, Wcomb, sidx);
    convi_kernel<<<(int)(((size_t)MN * KP + 255) / 256), 256>>>(inp);
    convw_kernel<<<(2 * GN * KP + 255) / 256, 256>>>(Wih_f, Wih_b);
    proj_mma<<<dim3(MN / 128, GN / 96, 2), 256, PSMEM>>>(bih_f, bih_b);
    persist_kernel<<<dim3(16, 4, 2), 256, SMEM_TOTAL>>>(Whh_f, Whh_b, bhh_f, bhh_b,
                                                        slen_s, sidx);
    attn_kernel<<<BN, 256>>>(seqlen, out);
}